// round 14
// baseline (speedup 1.0000x reference)
#include <cuda_runtime.h>
#include <cuda_bf16.h>
#include <stdint.h>
#include <math.h>

#define BB 8
#define SS 512
#define DD 768
#define NHH 12
#define HDD 64
#define FFF 3072
#define NLL 12
#define MT (BB*SS)

__device__ float g_h[MT*DD];
__device__ float g_q[MT*DD];
__device__ float g_ctx[MT*DD];
__device__ float g_a[MT*DD];
__device__ float g_f[MT*FFF];
__device__ float g_o[MT*DD];
__device__ float g_o2[MT*DD];
__device__ float g_o3[MT*DD];
__device__ float g_o4[MT*DD];
__device__ float g_hmean[BB*DD];
__device__ float g_cw[BB*HDD];
__device__ float g_ginv[BB*HDD*HDD];
__device__ __nv_bfloat16 g_wq_h[NLL*DD*DD], g_wq_l[NLL*DD*DD];
__device__ __nv_bfloat16 g_wk_h[NLL*DD*DD], g_wk_l[NLL*DD*DD];
__device__ __nv_bfloat16 g_wv_h[NLL*DD*DD], g_wv_l[NLL*DD*DD];
__device__ __nv_bfloat16 g_wi_h[(size_t)NLL*DD*FFF], g_wi_l[(size_t)NLL*DD*FFF];
__device__ __nv_bfloat16 g_wo_h[(size_t)NLL*FFF*DD], g_wo_l[(size_t)NLL*FFF*DD];
__device__ __nv_bfloat16 g_hh[MT*DD], g_hl[MT*DD];
__device__ __nv_bfloat16 g_ah[MT*DD], g_al[MT*DD];
__device__ __nv_bfloat16 g_fh[MT*FFF], g_fl[MT*FFF];
__device__ __nv_bfloat16 g_kh[MT*DD], g_kl[MT*DD];
__device__ __nv_bfloat16 g_vh[MT*DD], g_vl[MT*DD];
__device__ __nv_bfloat16 g_qgh[MT*DD], g_qgl[MT*DD];

__device__ __forceinline__ void ldsm_x4(uint32_t& r0, uint32_t& r1, uint32_t& r2, uint32_t& r3, uint32_t a)
{ asm volatile("ldmatrix.sync.aligned.m8n8.x4.shared.b16 {%0,%1,%2,%3},[%4];" : "=r"(r0),"=r"(r1),"=r"(r2),"=r"(r3) : "r"(a)); }
__device__ __forceinline__ void ldsm_x4_t(uint32_t& r0, uint32_t& r1, uint32_t& r2, uint32_t& r3, uint32_t a)
{ asm volatile("ldmatrix.sync.aligned.m8n8.x4.trans.shared.b16 {%0,%1,%2,%3},[%4];" : "=r"(r0),"=r"(r1),"=r"(r2),"=r"(r3) : "r"(a)); }
__device__ __forceinline__ void mma_bf16(float* c, const uint32_t* a, const uint32_t* b)
{ asm volatile("mma.sync.aligned.m16n8k16.row.col.f32.bf16.bf16.f32 {%0,%1,%2,%3},{%4,%5,%6,%7},{%8,%9},{%0,%1,%2,%3};"
               : "+f"(c[0]),"+f"(c[1]),"+f"(c[2]),"+f"(c[3])
               : "r"(a[0]),"r"(a[1]),"r"(a[2]),"r"(a[3]),"r"(b[0]),"r"(b[1])); }
__device__ __forceinline__ float gelu(float x) { return 0.5f*x*(1.f+erff(x*0.70710678118654752f)); }
__device__ __forceinline__ uint32_t packpair(float x, float y, uint32_t& lo)
{
    __nv_bfloat162 h = __floats2bfloat162_rn(x, y);
    __nv_bfloat162 l = __floats2bfloat162_rn(x-__low2float(h), y-__high2float(h));
    lo = *(uint32_t*)&l; return *(uint32_t*)&h;
}
__device__ __forceinline__ void cp16(uint32_t s, const void* g)
{ asm volatile("cp.async.cg.shared.global [%0],[%1],16;" :: "r"(s),"l"(g) : "memory"); }

__global__ __launch_bounds__(256)
void split_w_kernel(const float* __restrict__ src, __nv_bfloat16* __restrict__ dh,
                    __nv_bfloat16* __restrict__ dl, int n4)
{
    for (int i = blockIdx.x*256 + threadIdx.x; i < n4; i += gridDim.x*256) {
        float4 v = ((const float4*)src)[i];
        uint32_t l0, h0 = packpair(v.x, v.y, l0);
        uint32_t l1, h1 = packpair(v.z, v.w, l1);
        ((uint32_t*)dh)[i*2] = h0; ((uint32_t*)dh)[i*2+1] = h1;
        ((uint32_t*)dl)[i*2] = l0; ((uint32_t*)dl)[i*2+1] = l1;
    }
}

// ================= GEMM core ================
#define GRA 40
#define GRB 136
#define GASZ (128*GRA)
#define GBSZ (32*GRB)
#define GSTG_B ((2*GASZ + 2*GBSZ)*2)
#define G_SMEM (2*GSTG_B)

__device__ __forceinline__ void gemm_core(
    const __nv_bfloat16* Ah, const __nv_bfloat16* Al, int lda,
    const __nv_bfloat16* Wh, const __nv_bfloat16* Wl, int ldw,
    const float* bias, float* C, __nv_bfloat16* Ch, __nv_bfloat16* Cl, int ldc,
    int K, int act, int bm, int bn, int addb)
{
    extern __shared__ char smem[];
    const int tid = threadIdx.x, warp = tid >> 5, lane = tid & 31;
    const int wm = (warp & 3) * 32, wn = (warp >> 2) * 64;
    const uint32_t sb = (uint32_t)__cvta_generic_to_shared(smem);
    const int KT = K >> 5;
    float acc[2][8][4] = {};

    #define ISSUE(buf, k0) do { \
        uint32_t st = sb + (uint32_t)(buf)*GSTG_B; \
        _Pragma("unroll") for (int kk = 0; kk < 2; kk++) { \
            int ch = tid + kk*256; \
            int r = ch >> 2, o = (ch & 3) * 8; \
            uint32_t d = st + (uint32_t)(r*GRA + o)*2; \
            cp16(d,          Ah + (size_t)(bm+r)*lda + (k0) + o); \
            cp16(d + GASZ*2, Al + (size_t)(bm+r)*lda + (k0) + o); \
            int r2 = ch >> 4, o2 = (ch & 15) * 8; \
            uint32_t d2 = st + (uint32_t)(2*GASZ + r2*GRB + o2)*2; \
            cp16(d2,          Wh + (size_t)((k0)+r2)*ldw + bn + o2); \
            cp16(d2 + GBSZ*2, Wl + (size_t)((k0)+r2)*ldw + bn + o2); \
        } \
        asm volatile("cp.async.commit_group;" ::: "memory"); \
    } while(0)

    ISSUE(0, 0);
    for (int t = 0; t < KT; t++) {
        if (t + 1 < KT) { ISSUE((t+1)&1, (t+1)*32); asm volatile("cp.async.wait_group 1;" ::: "memory"); }
        else            { asm volatile("cp.async.wait_group 0;" ::: "memory"); }
        __syncthreads();
        uint32_t base = sb + (uint32_t)(t & 1) * GSTG_B;
        uint32_t a0b = base, a1b = base + GASZ*2, b0b = base + 2*GASZ*2, b1b = base + (2*GASZ+GBSZ)*2;
        #pragma unroll
        for (int ks = 0; ks < 2; ks++) {
            uint32_t a0[2][4], a1[2][4];
            #pragma unroll
            for (int i = 0; i < 2; i++) {
                uint32_t off = (uint32_t)(((wm + i*16 + (lane&15))*GRA + ks*16 + ((lane>>4)<<3))*2);
                ldsm_x4(a0[i][0],a0[i][1],a0[i][2],a0[i][3], a0b+off);
                ldsm_x4(a1[i][0],a1[i][1],a1[i][2],a1[i][3], a1b+off);
            }
            #pragma unroll
            for (int j = 0; j < 4; j++) {
                uint32_t boff = (uint32_t)(((ks*16 + (lane&15))*GRB + wn + j*16 + ((lane>>4)<<3))*2);
                uint32_t h0,h1,h2,h3, l0,l1,l2,l3;
                ldsm_x4_t(h0,h1,h2,h3, b0b+boff);
                ldsm_x4_t(l0,l1,l2,l3, b1b+boff);
                uint32_t bh0[2]={h0,h1}, bh1[2]={h2,h3}, bl0[2]={l0,l1}, bl1[2]={l2,l3};
                #pragma unroll
                for (int i = 0; i < 2; i++) {
                    mma_bf16(acc[i][j*2],   a0[i], bh0); mma_bf16(acc[i][j*2],   a0[i], bl0); mma_bf16(acc[i][j*2],   a1[i], bh0);
                    mma_bf16(acc[i][j*2+1], a0[i], bh1); mma_bf16(acc[i][j*2+1], a0[i], bl1); mma_bf16(acc[i][j*2+1], a1[i], bh1);
                }
            }
        }
        __syncthreads();
    }
    #undef ISSUE

    #pragma unroll
    for (int i = 0; i < 2; i++) {
        int r0 = bm + wm + i*16 + (lane >> 2);
        #pragma unroll
        for (int j = 0; j < 8; j++) {
            int c0 = bn + wn + j*8 + (lane & 3)*2;
            float b0v = addb ? bias[c0] : 0.f, b1v = addb ? bias[c0+1] : 0.f;
            float v0 = acc[i][j][0]+b0v, v1 = acc[i][j][1]+b1v;
            float v2 = acc[i][j][2]+b0v, v3 = acc[i][j][3]+b1v;
            if (act) { v0 = gelu(v0); v1 = gelu(v1); v2 = gelu(v2); v3 = gelu(v3); }
            if (C) {
                *(float2*)&C[(size_t)r0*ldc + c0]     = make_float2(v0, v1);
                *(float2*)&C[(size_t)(r0+8)*ldc + c0] = make_float2(v2, v3);
            }
            if (Ch) {
                uint32_t lo, hi = packpair(v0, v1, lo);
                *(uint32_t*)&Ch[(size_t)r0*ldc + c0] = hi; *(uint32_t*)&Cl[(size_t)r0*ldc + c0] = lo;
                hi = packpair(v2, v3, lo);
                *(uint32_t*)&Ch[(size_t)(r0+8)*ldc + c0] = hi; *(uint32_t*)&Cl[(size_t)(r0+8)*ldc + c0] = lo;
            }
        }
    }
}

__global__ __launch_bounds__(256, 2)
void gemm_kernel(const __nv_bfloat16* __restrict__ Ah, const __nv_bfloat16* __restrict__ Al,
                 const __nv_bfloat16* __restrict__ Wh, const __nv_bfloat16* __restrict__ Wl,
                 const float* __restrict__ bias, float* __restrict__ C,
                 __nv_bfloat16* __restrict__ Ch, __nv_bfloat16* __restrict__ Cl, int N, int K, int act)
{ gemm_core(Ah, Al, K, Wh, Wl, N, bias, C, Ch, Cl, N, K, act, blockIdx.y*128, blockIdx.x*128, 1); }

// fused QKV: Q -> fp32 (qg input); K,V -> bf16 pairs (flash input)
__global__ __launch_bounds__(256, 2)
void gemm_qkv_kernel(const __nv_bfloat16* __restrict__ Ah, const __nv_bfloat16* __restrict__ Al,
                     const __nv_bfloat16* Wqh, const __nv_bfloat16* Wql,
                     const __nv_bfloat16* Wkh, const __nv_bfloat16* Wkl,
                     const __nv_bfloat16* Wvh, const __nv_bfloat16* Wvl,
                     const float* b0, const float* b1, const float* b2,
                     float* q, __nv_bfloat16* kh, __nv_bfloat16* kl,
                     __nv_bfloat16* vh, __nv_bfloat16* vl)
{
    int sel = blockIdx.x / 6, bn = (blockIdx.x % 6) * 128;
    const __nv_bfloat16* Wh = sel==0?Wqh:sel==1?Wkh:Wvh;
    const __nv_bfloat16* Wl = sel==0?Wql:sel==1?Wkl:Wvl;
    const float* bias = sel==0?b0:sel==1?b1:b2;
    gemm_core(Ah, Al, DD, Wh, Wl, DD, bias,
              sel==0?q:nullptr, sel==1?kh:sel==2?vh:nullptr, sel==1?kl:sel==2?vl:nullptr,
              DD, DD, 0, blockIdx.y*128, bn, 1);
}

// 4-way split-K for Wo
__global__ __launch_bounds__(256, 2)
void gemm_splitk_kernel(const __nv_bfloat16* __restrict__ Ah, const __nv_bfloat16* __restrict__ Al,
                        const __nv_bfloat16* __restrict__ Wh, const __nv_bfloat16* __restrict__ Wl,
                        const float* __restrict__ bias,
                        float* __restrict__ C0, float* __restrict__ C1,
                        float* __restrict__ C2, float* __restrict__ C3)
{
    int z = blockIdx.z;
    const int KQ = FFF/4;
    float* C = z==0?C0:z==1?C1:z==2?C2:C3;
    gemm_core(Ah + z*KQ, Al + z*KQ, FFF,
              Wh + (size_t)(z*KQ)*DD, Wl + (size_t)(z*KQ)*DD, DD,
              bias, C, nullptr, nullptr, DD, KQ, 0, blockIdx.y*128, blockIdx.x*128, z == 0);
}

// ================= fused flash attention (cp.async pre-split, occ 2) ================
#define SCR 72
#define FQSZ (128*SCR)          // elems per Q buffer
#define FKSZ (64*SCR)
#define FQ0 0
#define FQ1 FQSZ
#define FK0 (2*FQSZ)
#define FK1 (FK0 + FKSZ)
#define FV0 (FK0 + 2*FKSZ)
#define FV1 (FK0 + 3*FKSZ)
#define FL_SMEM ((2*FQSZ + 4*FKSZ)*2)

__global__ __launch_bounds__(256, 2)
void flash_kernel(const __nv_bfloat16* __restrict__ qh, const __nv_bfloat16* __restrict__ ql,
                  const __nv_bfloat16* __restrict__ kh, const __nv_bfloat16* __restrict__ kl,
                  const __nv_bfloat16* __restrict__ vh, const __nv_bfloat16* __restrict__ vl,
                  float* __restrict__ ctx)
{
    extern __shared__ __nv_bfloat16 fs[];
    const int bh = blockIdx.y, b = bh / NHH, h = bh % NHH;
    const int i0 = blockIdx.x * 128;
    const int tid = threadIdx.x, warp = tid >> 5, lane = tid & 31;
    const int wm = warp * 16;
    const uint32_t sbase = (uint32_t)__cvta_generic_to_shared(fs);

    // stage Q pairs via cp.async: 128 rows x 64 cols, hi+lo = 2048 x 16B chunks
    #pragma unroll
    for (int it = 0; it < 4; it++) {
        int ch = it*256 + tid, row = ch >> 3, col = (ch & 7) * 8;
        uint32_t d = sbase + (uint32_t)(row*SCR + col)*2;
        size_t gof = (size_t)(b*SS + i0 + row)*DD + h*HDD + col;
        cp16(d,            qh + gof);
        cp16(d + FQSZ*2,   ql + gof);
    }
    asm volatile("cp.async.commit_group;" ::: "memory");

    const uint32_t q0b = sbase + FQ0*2, q1b = sbase + FQ1*2;
    const uint32_t k0b = sbase + FK0*2, k1b = sbase + FK1*2;
    const uint32_t v0b = sbase + FV0*2, v1b = sbase + FV1*2;

    float m0 = -1e30f, m1 = -1e30f, l0 = 0.f, l1 = 0.f;
    float acc[8][4] = {};

    for (int j0 = 0; j0 < SS; j0 += 64) {
        __syncthreads();   // previous compute done before overwrite
        #pragma unroll
        for (int it = 0; it < 2; it++) {
            int ch = it*256 + tid, row = ch >> 3, col = (ch & 7) * 8;
            uint32_t d = sbase + (uint32_t)(row*SCR + col)*2;
            size_t gof = (size_t)(b*SS + j0 + row)*DD + h*HDD + col;
            cp16(d + FK0*2, kh + gof);
            cp16(d + FK1*2, kl + gof);
            cp16(d + FV0*2, vh + gof);
            cp16(d + FV1*2, vl + gof);
        }
        asm volatile("cp.async.commit_group;" ::: "memory");
        asm volatile("cp.async.wait_group 0;" ::: "memory");
        __syncthreads();

        float s[8][4] = {};
        #pragma unroll
        for (int ks = 0; ks < 4; ks++) {
            uint32_t aoff = (uint32_t)(((wm + (lane&15))*SCR + ks*16 + ((lane>>4)<<3))*2);
            uint32_t a0[4], a1[4];
            ldsm_x4(a0[0],a0[1],a0[2],a0[3], q0b+aoff);
            ldsm_x4(a1[0],a1[1],a1[2],a1[3], q1b+aoff);
            #pragma unroll
            for (int jt = 0; jt < 4; jt++) {
                uint32_t boff = (uint32_t)(((jt*16 + (lane&15))*SCR + ks*16 + ((lane>>4)<<3))*2);
                uint32_t r0,r1,r2,r3;
                uint32_t bh0[2], bh1[2], bl0[2], bl1[2];
                ldsm_x4(r0,r1,r2,r3, k0b+boff);
                bh0[0]=r0; bh0[1]=r2; bh1[0]=r1; bh1[1]=r3;
                ldsm_x4(r0,r1,r2,r3, k1b+boff);
                bl0[0]=r0; bl0[1]=r2; bl1[0]=r1; bl1[1]=r3;
                mma_bf16(s[jt*2],   a0, bh0); mma_bf16(s[jt*2],   a0, bl0); mma_bf16(s[jt*2],   a1, bh0);
                mma_bf16(s[jt*2+1], a0, bh1); mma_bf16(s[jt*2+1], a0, bl1); mma_bf16(s[jt*2+1], a1, bh1);
            }
        }
        float mt0 = -1e30f, mt1 = -1e30f;
        #pragma unroll
        for (int n = 0; n < 8; n++) {
            s[n][0] *= 0.125f; s[n][1] *= 0.125f; s[n][2] *= 0.125f; s[n][3] *= 0.125f;
            mt0 = fmaxf(mt0, fmaxf(s[n][0], s[n][1]));
            mt1 = fmaxf(mt1, fmaxf(s[n][2], s[n][3]));
        }
        #pragma unroll
        for (int o = 1; o < 4; o <<= 1) {
            mt0 = fmaxf(mt0, __shfl_xor_sync(~0u, mt0, o));
            mt1 = fmaxf(mt1, __shfl_xor_sync(~0u, mt1, o));
        }
        float mn0 = fmaxf(m0, mt0), mn1 = fmaxf(m1, mt1);
        float al0 = expf(m0 - mn0), al1 = expf(m1 - mn1);
        float sum0 = 0.f, sum1 = 0.f;
        #pragma unroll
        for (int n = 0; n < 8; n++) {
            s[n][0] = expf(s[n][0]-mn0); s[n][1] = expf(s[n][1]-mn0);
            s[n][2] = expf(s[n][2]-mn1); s[n][3] = expf(s[n][3]-mn1);
            sum0 += s[n][0] + s[n][1]; sum1 += s[n][2] + s[n][3];
        }
        #pragma unroll
        for (int o = 1; o < 4; o <<= 1) {
            sum0 += __shfl_xor_sync(~0u, sum0, o);
            sum1 += __shfl_xor_sync(~0u, sum1, o);
        }
        m0 = mn0; m1 = mn1;
        l0 = l0*al0 + sum0; l1 = l1*al1 + sum1;
        #pragma unroll
        for (int n = 0; n < 8; n++) {
            acc[n][0] *= al0; acc[n][1] *= al0; acc[n][2] *= al1; acc[n][3] *= al1;
        }
        #pragma unroll
        for (int ks = 0; ks < 4; ks++) {
            uint32_t ph[4], pl[4];
            ph[0] = packpair(s[2*ks][0],   s[2*ks][1],   pl[0]);
            ph[1] = packpair(s[2*ks][2],   s[2*ks][3],   pl[1]);
            ph[2] = packpair(s[2*ks+1][0], s[2*ks+1][1], pl[2]);
            ph[3] = packpair(s[2*ks+1][2], s[2*ks+1][3], pl[3]);
            #pragma unroll
            for (int jt = 0; jt < 4; jt++) {
                uint32_t boff = (uint32_t)(((ks*16 + (lane&15))*SCR + jt*16 + ((lane>>4)<<3))*2);
                uint32_t r0,r1,r2,r3;
                uint32_t bh0[2], bh1[2], bl0[2], bl1[2];
                ldsm_x4_t(r0,r1,r2,r3, v0b+boff);
                bh0[0]=r0; bh0[1]=r1; bh1[0]=r2; bh1[1]=r3;
                ldsm_x4_t(r0,r1,r2,r3, v1b+boff);
                bl0[0]=r0; bl0[1]=r1; bl1[0]=r2; bl1[1]=r3;
                mma_bf16(acc[jt*2],   ph, bh0); mma_bf16(acc[jt*2],   ph, bl0); mma_bf16(acc[jt*2],   pl, bh0);
                mma_bf16(acc[jt*2+1], ph, bh1); mma_bf16(acc[jt*2+1], ph, bl1); mma_bf16(acc[jt*2+1], pl, bh1);
            }
        }
    }
    float il0 = 1.f / l0, il1 = 1.f / l1;
    int r0 = i0 + wm + (lane >> 2);
    #pragma unroll
    for (int n = 0; n < 8; n++) {
        int c0 = h*HDD + n*8 + (lane&3)*2;
        *(float2*)&ctx[(size_t)(b*SS + r0)*DD + c0]   = make_float2(acc[n][0]*il0, acc[n][1]*il0);
        *(float2*)&ctx[(size_t)(b*SS + r0+8)*DD + c0] = make_float2(acc[n][2]*il1, acc[n][3]*il1);
    }
}

// ---- LayerNorm family ----
#define LN_BODY(EXPR) \
    int t = blockIdx.x, tid = threadIdx.x; \
    __shared__ float red[256]; \
    size_t base = (size_t)t * DD; \
    float v[3]; float sum = 0.f; \
    _Pragma("unroll") for (int i = 0; i < 3; i++) { int d = tid + i*256; v[i] = (EXPR); sum += v[i]; } \
    red[tid] = sum; __syncthreads(); \
    for (int o = 128; o > 0; o >>= 1) { if (tid < o) red[tid] += red[tid+o]; __syncthreads(); } \
    float mean = red[0] * (1.0f/DD); __syncthreads(); \
    float vs = 0.f; \
    _Pragma("unroll") for (int i = 0; i < 3; i++) { float d0 = v[i]-mean; vs += d0*d0; } \
    red[tid] = vs; __syncthreads(); \
    for (int o = 128; o > 0; o >>= 1) { if (tid < o) red[tid] += red[tid+o]; __syncthreads(); } \
    float rstd = rsqrtf(red[0]*(1.0f/DD) + 1e-12f); \
    _Pragma("unroll") for (int i = 0; i < 3; i++) { int d = tid + i*256; \
        float vv = (v[i]-mean)*rstd*w[d] + bb[d]; out[base+d] = vv; \
        if (oh) { __nv_bfloat16 hb = __float2bfloat16(vv); oh[base+d] = hb; \
                  ol[base+d] = __float2bfloat16(vv - __bfloat162float(hb)); } }

__global__ __launch_bounds__(256)
void embed_ln_kernel(const int* __restrict__ ids, const int* __restrict__ tts,
                     const float* __restrict__ we, const float* __restrict__ pe, const float* __restrict__ te,
                     const float* __restrict__ w, const float* __restrict__ bb, float* __restrict__ out,
                     __nv_bfloat16* __restrict__ oh, __nv_bfloat16* __restrict__ ol)
{
    int s = blockIdx.x % SS;
    const float* wr = we + (size_t)ids[blockIdx.x] * DD;
    const float* pr = pe + (size_t)s * DD;
    const float* tr = te + (size_t)tts[blockIdx.x] * DD;
    LN_BODY(wr[d] + pr[d] + tr[d])
}
__global__ __launch_bounds__(256)
void add_ln_kernel(const float* __restrict__ x, const float* __restrict__ y,
                   const float* __restrict__ w, const float* __restrict__ bb, float* __restrict__ out,
                   __nv_bfloat16* __restrict__ oh, __nv_bfloat16* __restrict__ ol)
{ LN_BODY(x[base+d] + y[base+d]) }
__global__ __launch_bounds__(256)
void add_ln5_kernel(const float* __restrict__ x1, const float* __restrict__ x2,
                    const float* __restrict__ x3, const float* __restrict__ x4,
                    const float* __restrict__ y,
                    const float* __restrict__ w, const float* __restrict__ bb, float* __restrict__ out,
                    __nv_bfloat16* __restrict__ oh, __nv_bfloat16* __restrict__ ol)
{ LN_BODY(x1[base+d] + x2[base+d] + x3[base+d] + x4[base+d] + y[base+d]) }

// ---- metric path ----
__global__ __launch_bounds__(256)
void pool_kernel(const float* __restrict__ h, float* __restrict__ hmean)
{
    int b = blockIdx.x, c0 = blockIdx.y * 128, tid = threadIdx.x;
    int col = c0 + (tid & 127), rg = tid >> 7;
    __shared__ float part[256];
    float s = 0.f;
    for (int t = rg*256; t < rg*256 + 256; t++) s += h[((size_t)b*SS + t)*DD + col];
    part[tid] = s; __syncthreads();
    if (tid < 128) hmean[b*DD + col] = (part[tid] + part[tid+128]) * (1.0f/SS);
}
__global__ __launch_bounds__(256)
void cw_kernel(const float* __restrict__ hmean, const float* __restrict__ Wcp,
               const float* __restrict__ bcp, float* __restrict__ cw)
{
    int b = blockIdx.x, tid = threadIdx.x;
    __shared__ float hm[DD]; __shared__ float part[256];
    for (int i = tid; i < DD; i += 256) hm[i] = hmean[b*DD + i];
    __syncthreads();
    int j = tid & 63, d0 = (tid >> 6) * 192;
    float acc = 0.f;
    #pragma unroll 4
    for (int d = d0; d < d0 + 192; d++) acc = fmaf(hm[d], Wcp[(size_t)d*DD + j], acc);
    part[tid] = acc; __syncthreads();
    if (tid < 64) {
        float y = bcp[tid] + part[tid] + part[tid+64] + part[tid+128] + part[tid+192];
        cw[b*HDD + tid] = 1.f / (1.f + expf(-y));
    }
}
__global__ __launch_bounds__(256)
void ginv_kernel(const float* __restrict__ Lm_l, const float* __restrict__ diag_l,
                 const float* __restrict__ cw, float* __restrict__ ginv)
{
    int b = blockIdx.x, tid = threadIdx.x;
    __shared__ float L[64][64]; __shared__ float A[64][65]; __shared__ float fcol[64];
    for (int it = 0; it < 16; it++) { int idx = it*256+tid; L[idx>>6][idx&63] = Lm_l[idx] * cw[b*HDD + (idx>>6)]; }
    __syncthreads();
    for (int it = 0; it < 16; it++) {
        int idx = it*256+tid, i = idx>>6, j = idx&63;
        float s = 0.f;
        for (int t2 = 0; t2 < 64; t2++) s = fmaf(L[i][t2], L[j][t2], s);
        if (i == j) s += diag_l[i] + 1e-6f + 0.1f;
        A[i][j] = s;
    }
    __syncthreads();
    for (int it = 0; it < 16; it++) { int idx = it*256+tid; L[idx>>6][idx&63] = ((idx>>6)==(idx&63)) ? 1.f : 0.f; }
    __syncthreads();
    for (int p = 0; p < 64; p++) {
        float ip = 1.f / A[p][p];
        float myf = (tid < 64) ? A[tid][p] : 0.f;
        __syncthreads();
        if (tid < 64) A[p][tid] *= ip; else if (tid < 128) L[p][tid-64] *= ip;
        if (tid < 64) fcol[tid] = (tid == p) ? 0.f : myf;
        __syncthreads();
        for (int it = 0; it < 32; it++) {
            int idx = it*256+tid, r = idx>>7, c = idx&127;
            if (r != p) { if (c < 64) A[r][c] -= fcol[r]*A[p][c]; else L[r][c-64] -= fcol[r]*L[p][c-64]; }
        }
        __syncthreads();
    }
    for (int it = 0; it < 16; it++) { int idx = it*256+tid; ginv[b*(HDD*HDD) + idx] = L[idx>>6][idx&63]; }
}
// qg = q @ ginv -> bf16 hi/lo pairs
__global__ __launch_bounds__(256)
void qg_kernel(const float* __restrict__ q, const float* __restrict__ ginv,
               __nv_bfloat16* __restrict__ qgh, __nv_bfloat16* __restrict__ qgl)
{
    int m0 = blockIdx.x * 64, h = blockIdx.y, b = m0 / SS, tid = threadIdx.x;
    __shared__ float Qt[64][65]; __shared__ float G[64][65];
    const float* gb = ginv + b * (HDD*HDD);
    #pragma unroll
    for (int it = 0; it < 16; it++) {
        int idx = it*256+tid, r = idx>>6, c = idx&63;
        Qt[c][r] = q[(size_t)(m0+r)*DD + h*HDD + c];
        G[r][c] = gb[idx];
    }
    __syncthreads();
    int tx = tid & 15, ty = tid >> 4;
    float acc[4][4] = {};
    for (int d = 0; d < 64; d++) {
        float a[4], bb2[4];
        #pragma unroll
        for (int i = 0; i < 4; i++) a[i] = Qt[d][ty*4+i];
        #pragma unroll
        for (int j = 0; j < 4; j++) bb2[j] = G[d][tx*4+j];
        #pragma unroll
        for (int i = 0; i < 4; i++)
            #pragma unroll
            for (int j = 0; j < 4; j++) acc[i][j] = fmaf(a[i], bb2[j], acc[i][j]);
    }
    #pragma unroll
    for (int i = 0; i < 4; i++) {
        size_t of = (size_t)(m0+ty*4+i)*DD + h*HDD + tx*4;
        uint32_t lo0, hi0 = packpair(acc[i][0], acc[i][1], lo0);
        uint32_t lo1, hi1 = packpair(acc[i][2], acc[i][3], lo1);
        *(uint32_t*)&qgh[of]   = hi0; *(uint32_t*)&qgh[of+2] = hi1;
        *(uint32_t*)&qgl[of]   = lo0; *(uint32_t*)&qgl[of+2] = lo1;
    }
}

#define SYM(p, s) cudaGetSymbolAddress((void**)&p, s)

extern "C" void kernel_launch(void* const* d_in, const int* in_sizes, int n_in, void* d_out, int out_size)
{
    const int* ids = (const int*)d_in[0];
    const int* tts = (const int*)d_in[1];
    const float* we = (const float*)d_in[2];
    const float* pe = (const float*)d_in[3];
    const float* te = (const float*)d_in[4];
    const float* lnew = (const float*)d_in[5];
    const float* lneb = (const float*)d_in[6];
    const float* Wq = (const float*)d_in[7];
    const float* bq = (const float*)d_in[8];
    const float* Wk = (const float*)d_in[9];
    const float* bk = (const float*)d_in[10];
    const float* Wv = (const float*)d_in[11];
    const float* bv = (const float*)d_in[12];
    const float* Lm = (const float*)d_in[13];
    const float* dg = (const float*)d_in[14];
    const float* Wcp = (const float*)d_in[15];
    const float* bcp = (const float*)d_in[16];
    const float* Wi = (const float*)d_in[17];
    const float* bi = (const float*)d_in[18];
    const float* Wo = (const float*)d_in[19];
    const float* bo = (const float*)d_in[20];
    const float* l1w = (const float*)d_in[21];
    const float* l1b = (const float*)d_in[22];
    const float* l2w = (const float*)d_in[23];
    const float* l2b = (const float*)d_in[24];

    float *h,*q,*ctx,*a,*f,*o,*o2,*o3,*o4,*hmean,*cw,*ginv;
    __nv_bfloat16 *wqh,*wql,*wkh,*wkl,*wvh,*wvl,*wih,*wil,*woh,*wol;
    __nv_bfloat16 *hh,*hl,*ah,*al,*fh,*fl,*kh,*kl,*vh,*vl,*qgh,*qgl;
    SYM(h,g_h); SYM(q,g_q); SYM(ctx,g_ctx); SYM(a,g_a); SYM(f,g_f);
    SYM(o,g_o); SYM(o2,g_o2); SYM(o3,g_o3); SYM(o4,g_o4);
    SYM(hmean,g_hmean); SYM(cw,g_cw); SYM(ginv,g_ginv);
    SYM(wqh,g_wq_h); SYM(wql,g_wq_l); SYM(wkh,g_wk_h); SYM(wkl,g_wk_l);
    SYM(wvh,g_wv_h); SYM(wvl,g_wv_l); SYM(wih,g_wi_h); SYM(wil,g_wi_l);
    SYM(woh,g_wo_h); SYM(wol,g_wo_l);
    SYM(hh,g_hh); SYM(hl,g_hl); SYM(ah,g_ah); SYM(al,g_al); SYM(fh,g_fh); SYM(fl,g_fl);
    SYM(kh,g_kh); SYM(kl,g_kl); SYM(vh,g_vh); SYM(vl,g_vl); SYM(qgh,g_qgh); SYM(qgl,g_qgl);

    cudaFuncSetAttribute(gemm_kernel,        cudaFuncAttributeMaxDynamicSharedMemorySize, G_SMEM);
    cudaFuncSetAttribute(gemm_qkv_kernel,    cudaFuncAttributeMaxDynamicSharedMemorySize, G_SMEM);
    cudaFuncSetAttribute(gemm_splitk_kernel, cudaFuncAttributeMaxDynamicSharedMemorySize, G_SMEM);
    cudaFuncSetAttribute(flash_kernel,       cudaFuncAttributeMaxDynamicSharedMemorySize, FL_SMEM);

    split_w_kernel<<<1024, 256>>>(Wq, wqh, wql, NLL*DD*DD/4);
    split_w_kernel<<<1024, 256>>>(Wk, wkh, wkl, NLL*DD*DD/4);
    split_w_kernel<<<1024, 256>>>(Wv, wvh, wvl, NLL*DD*DD/4);
    split_w_kernel<<<2048, 256>>>(Wi, wih, wil, NLL*DD*FFF/4);
    split_w_kernel<<<2048, 256>>>(Wo, woh, wol, NLL*FFF*DD/4);

    embed_ln_kernel<<<MT, 256>>>(ids, tts, we, pe, te, lnew, lneb, h, hh, hl);

    for (int l = 0; l < NLL; l++) {
        size_t od = (size_t)l*DD*DD, of = (size_t)l*DD*FFF;

        gemm_qkv_kernel<<<dim3(18, 32), 256, G_SMEM>>>(hh, hl, wqh+od, wql+od, wkh+od, wkl+od,
            wvh+od, wvl+od, bq + l*DD, bk + l*DD, bv + l*DD, q, kh, kl, vh, vl);

        pool_kernel<<<dim3(BB, 6), 256>>>(h, hmean);
        cw_kernel<<<BB, 256>>>(hmean, Wcp + od, bcp + l*DD, cw);
        ginv_kernel<<<BB, 256>>>(Lm + (size_t)l*DD*64, dg + l*DD, cw, ginv);

        qg_kernel<<<dim3(MT/64, NHH), 256>>>(q, ginv, qgh, qgl);
        flash_kernel<<<dim3(SS/128, BB*NHH), 256, FL_SMEM>>>(qgh, qgl, kh, kl, vh, vl, ctx);

        add_ln_kernel<<<MT, 256>>>(ctx, h, l1w + l*DD, l1b + l*DD, a, ah, al);

        gemm_kernel<<<dim3(FFF/128, 32), 256, G_SMEM>>>(ah, al, wih+of, wil+of,
            bi + (size_t)l*FFF, f, fh, fl, FFF, DD, 1);
        gemm_splitk_kernel<<<dim3(DD/128, 32, 4), 256, G_SMEM>>>(fh, fl, woh+of, wol+of,
            bo + l*DD, o, o2, o3, o4);

        float* out_h = (l == NLL-1) ? (float*)d_out : h;
        add_ln5_kernel<<<MT, 256>>>(o, o2, o3, o4, a, l2w + l*DD, l2b + l*DD, out_h,
                                    (l == NLL-1) ? nullptr : hh, (l == NLL-1) ? nullptr : hl);
    }
}

// round 15
// speedup vs baseline: 1.0121x; 1.0121x over previous
#include <cuda_runtime.h>
#include <cuda_bf16.h>
#include <stdint.h>
#include <math.h>

#define BB 8
#define SS 512
#define DD 768
#define NHH 12
#define HDD 64
#define FFF 3072
#define NLL 12
#define MT (BB*SS)

__device__ float g_h[MT*DD];
__device__ float g_ctx[MT*DD];
__device__ float g_a[MT*DD];
__device__ float g_f[MT*FFF];
__device__ float g_o[MT*DD];
__device__ float g_o2[MT*DD];
__device__ float g_hmean[BB*DD];
__device__ float g_cw[BB*HDD];
__device__ float g_ginv[BB*HDD*HDD];
__device__ __nv_bfloat16 g_wq_h[NLL*DD*DD], g_wq_l[NLL*DD*DD];
__device__ __nv_bfloat16 g_wk_h[NLL*DD*DD], g_wk_l[NLL*DD*DD];
__device__ __nv_bfloat16 g_wv_h[NLL*DD*DD], g_wv_l[NLL*DD*DD];
__device__ __nv_bfloat16 g_wi_h[(size_t)NLL*DD*FFF], g_wi_l[(size_t)NLL*DD*FFF];
__device__ __nv_bfloat16 g_wo_h[(size_t)NLL*FFF*DD], g_wo_l[(size_t)NLL*FFF*DD];
__device__ __nv_bfloat16 g_hh[MT*DD], g_hl[MT*DD];
__device__ __nv_bfloat16 g_ah[MT*DD], g_al[MT*DD];
__device__ __nv_bfloat16 g_fh[MT*FFF], g_fl[MT*FFF];
__device__ __nv_bfloat16 g_kh[MT*DD], g_kl[MT*DD];
__device__ __nv_bfloat16 g_vh[MT*DD], g_vl[MT*DD];
__device__ __nv_bfloat16 g_qh[MT*DD], g_ql[MT*DD];

__device__ __forceinline__ void ldsm_x4(uint32_t& r0, uint32_t& r1, uint32_t& r2, uint32_t& r3, uint32_t a)
{ asm volatile("ldmatrix.sync.aligned.m8n8.x4.shared.b16 {%0,%1,%2,%3},[%4];" : "=r"(r0),"=r"(r1),"=r"(r2),"=r"(r3) : "r"(a)); }
__device__ __forceinline__ void ldsm_x4_t(uint32_t& r0, uint32_t& r1, uint32_t& r2, uint32_t& r3, uint32_t a)
{ asm volatile("ldmatrix.sync.aligned.m8n8.x4.trans.shared.b16 {%0,%1,%2,%3},[%4];" : "=r"(r0),"=r"(r1),"=r"(r2),"=r"(r3) : "r"(a)); }
__device__ __forceinline__ void mma_bf16(float* c, const uint32_t* a, const uint32_t* b)
{ asm volatile("mma.sync.aligned.m16n8k16.row.col.f32.bf16.bf16.f32 {%0,%1,%2,%3},{%4,%5,%6,%7},{%8,%9},{%0,%1,%2,%3};"
               : "+f"(c[0]),"+f"(c[1]),"+f"(c[2]),"+f"(c[3])
               : "r"(a[0]),"r"(a[1]),"r"(a[2]),"r"(a[3]),"r"(b[0]),"r"(b[1])); }
__device__ __forceinline__ float gelu(float x) { return 0.5f*x*(1.f+erff(x*0.70710678118654752f)); }
__device__ __forceinline__ uint32_t packpair(float x, float y, uint32_t& lo)
{
    __nv_bfloat162 h = __floats2bfloat162_rn(x, y);
    __nv_bfloat162 l = __floats2bfloat162_rn(x-__low2float(h), y-__high2float(h));
    lo = *(uint32_t*)&l; return *(uint32_t*)&h;
}
__device__ __forceinline__ void cp16(uint32_t s, const void* g)
{ asm volatile("cp.async.cg.shared.global [%0],[%1],16;" :: "r"(s),"l"(g) : "memory"); }

__global__ __launch_bounds__(256)
void split_w_kernel(const float* __restrict__ src, __nv_bfloat16* __restrict__ dh,
                    __nv_bfloat16* __restrict__ dl, int n4)
{
    for (int i = blockIdx.x*256 + threadIdx.x; i < n4; i += gridDim.x*256) {
        float4 v = ((const float4*)src)[i];
        uint32_t l0, h0 = packpair(v.x, v.y, l0);
        uint32_t l1, h1 = packpair(v.z, v.w, l1);
        ((uint32_t*)dh)[i*2] = h0; ((uint32_t*)dh)[i*2+1] = h1;
        ((uint32_t*)dl)[i*2] = l0; ((uint32_t*)dl)[i*2+1] = l1;
    }
}

// ================= GEMM core ================
#define GRA 40
#define GRB 136
#define GASZ (128*GRA)
#define GBSZ (32*GRB)
#define GSTG_B ((2*GASZ + 2*GBSZ)*2)
#define G_SMEM (2*GSTG_B)

__device__ __forceinline__ void gemm_core(
    const __nv_bfloat16* Ah, const __nv_bfloat16* Al, int lda,
    const __nv_bfloat16* Wh, const __nv_bfloat16* Wl, int ldw,
    const float* bias, float* C, __nv_bfloat16* Ch, __nv_bfloat16* Cl, int ldc,
    int K, int act, int bm, int bn, int addb)
{
    extern __shared__ char smem[];
    const int tid = threadIdx.x, warp = tid >> 5, lane = tid & 31;
    const int wm = (warp & 3) * 32, wn = (warp >> 2) * 64;
    const uint32_t sb = (uint32_t)__cvta_generic_to_shared(smem);
    const int KT = K >> 5;
    float acc[2][8][4] = {};

    #define ISSUE(buf, k0) do { \
        uint32_t st = sb + (uint32_t)(buf)*GSTG_B; \
        _Pragma("unroll") for (int kk = 0; kk < 2; kk++) { \
            int ch = tid + kk*256; \
            int r = ch >> 2, o = (ch & 3) * 8; \
            uint32_t d = st + (uint32_t)(r*GRA + o)*2; \
            cp16(d,          Ah + (size_t)(bm+r)*lda + (k0) + o); \
            cp16(d + GASZ*2, Al + (size_t)(bm+r)*lda + (k0) + o); \
            int r2 = ch >> 4, o2 = (ch & 15) * 8; \
            uint32_t d2 = st + (uint32_t)(2*GASZ + r2*GRB + o2)*2; \
            cp16(d2,          Wh + (size_t)((k0)+r2)*ldw + bn + o2); \
            cp16(d2 + GBSZ*2, Wl + (size_t)((k0)+r2)*ldw + bn + o2); \
        } \
        asm volatile("cp.async.commit_group;" ::: "memory"); \
    } while(0)

    ISSUE(0, 0);
    for (int t = 0; t < KT; t++) {
        if (t + 1 < KT) { ISSUE((t+1)&1, (t+1)*32); asm volatile("cp.async.wait_group 1;" ::: "memory"); }
        else            { asm volatile("cp.async.wait_group 0;" ::: "memory"); }
        __syncthreads();
        uint32_t base = sb + (uint32_t)(t & 1) * GSTG_B;
        uint32_t a0b = base, a1b = base + GASZ*2, b0b = base + 2*GASZ*2, b1b = base + (2*GASZ+GBSZ)*2;
        #pragma unroll
        for (int ks = 0; ks < 2; ks++) {
            uint32_t a0[2][4], a1[2][4];
            #pragma unroll
            for (int i = 0; i < 2; i++) {
                uint32_t off = (uint32_t)(((wm + i*16 + (lane&15))*GRA + ks*16 + ((lane>>4)<<3))*2);
                ldsm_x4(a0[i][0],a0[i][1],a0[i][2],a0[i][3], a0b+off);
                ldsm_x4(a1[i][0],a1[i][1],a1[i][2],a1[i][3], a1b+off);
            }
            #pragma unroll
            for (int j = 0; j < 4; j++) {
                uint32_t boff = (uint32_t)(((ks*16 + (lane&15))*GRB + wn + j*16 + ((lane>>4)<<3))*2);
                uint32_t h0,h1,h2,h3, l0,l1,l2,l3;
                ldsm_x4_t(h0,h1,h2,h3, b0b+boff);
                ldsm_x4_t(l0,l1,l2,l3, b1b+boff);
                uint32_t bh0[2]={h0,h1}, bh1[2]={h2,h3}, bl0[2]={l0,l1}, bl1[2]={l2,l3};
                #pragma unroll
                for (int i = 0; i < 2; i++) {
                    mma_bf16(acc[i][j*2],   a0[i], bh0); mma_bf16(acc[i][j*2],   a0[i], bl0); mma_bf16(acc[i][j*2],   a1[i], bh0);
                    mma_bf16(acc[i][j*2+1], a0[i], bh1); mma_bf16(acc[i][j*2+1], a0[i], bl1); mma_bf16(acc[i][j*2+1], a1[i], bh1);
                }
            }
        }
        __syncthreads();
    }
    #undef ISSUE

    #pragma unroll
    for (int i = 0; i < 2; i++) {
        int r0 = bm + wm + i*16 + (lane >> 2);
        #pragma unroll
        for (int j = 0; j < 8; j++) {
            int c0 = bn + wn + j*8 + (lane & 3)*2;
            float b0v = addb ? bias[c0] : 0.f, b1v = addb ? bias[c0+1] : 0.f;
            float v0 = acc[i][j][0]+b0v, v1 = acc[i][j][1]+b1v;
            float v2 = acc[i][j][2]+b0v, v3 = acc[i][j][3]+b1v;
            if (act) { v0 = gelu(v0); v1 = gelu(v1); v2 = gelu(v2); v3 = gelu(v3); }
            if (C) {
                *(float2*)&C[(size_t)r0*ldc + c0]     = make_float2(v0, v1);
                *(float2*)&C[(size_t)(r0+8)*ldc + c0] = make_float2(v2, v3);
            }
            if (Ch) {
                uint32_t lo, hi = packpair(v0, v1, lo);
                *(uint32_t*)&Ch[(size_t)r0*ldc + c0] = hi; *(uint32_t*)&Cl[(size_t)r0*ldc + c0] = lo;
                hi = packpair(v2, v3, lo);
                *(uint32_t*)&Ch[(size_t)(r0+8)*ldc + c0] = hi; *(uint32_t*)&Cl[(size_t)(r0+8)*ldc + c0] = lo;
            }
        }
    }
}

__global__ __launch_bounds__(256, 2)
void gemm_kernel(const __nv_bfloat16* __restrict__ Ah, const __nv_bfloat16* __restrict__ Al,
                 const __nv_bfloat16* __restrict__ Wh, const __nv_bfloat16* __restrict__ Wl,
                 const float* __restrict__ bias, float* __restrict__ C,
                 __nv_bfloat16* __restrict__ Ch, __nv_bfloat16* __restrict__ Cl, int N, int K, int act)
{ gemm_core(Ah, Al, K, Wh, Wl, N, bias, C, Ch, Cl, N, K, act, blockIdx.y*128, blockIdx.x*128, 1); }

// fused QKV: all three outputs as bf16 hi/lo pairs
__global__ __launch_bounds__(256, 2)
void gemm_qkv_kernel(const __nv_bfloat16* __restrict__ Ah, const __nv_bfloat16* __restrict__ Al,
                     const __nv_bfloat16* Wqh, const __nv_bfloat16* Wql,
                     const __nv_bfloat16* Wkh, const __nv_bfloat16* Wkl,
                     const __nv_bfloat16* Wvh, const __nv_bfloat16* Wvl,
                     const float* b0, const float* b1, const float* b2,
                     __nv_bfloat16* qh, __nv_bfloat16* ql,
                     __nv_bfloat16* kh, __nv_bfloat16* kl,
                     __nv_bfloat16* vh, __nv_bfloat16* vl)
{
    int sel = blockIdx.x / 6, bn = (blockIdx.x % 6) * 128;
    const __nv_bfloat16* Wh = sel==0?Wqh:sel==1?Wkh:Wvh;
    const __nv_bfloat16* Wl = sel==0?Wql:sel==1?Wkl:Wvl;
    const float* bias = sel==0?b0:sel==1?b1:b2;
    __nv_bfloat16* Ch = sel==0?qh:sel==1?kh:vh;
    __nv_bfloat16* Cl = sel==0?ql:sel==1?kl:vl;
    gemm_core(Ah, Al, DD, Wh, Wl, DD, bias, nullptr, Ch, Cl, DD, DD, 0, blockIdx.y*128, bn, 1);
}

// 2-way split-K for Wo
__global__ __launch_bounds__(256, 2)
void gemm_splitk_kernel(const __nv_bfloat16* __restrict__ Ah, const __nv_bfloat16* __restrict__ Al,
                        const __nv_bfloat16* __restrict__ Wh, const __nv_bfloat16* __restrict__ Wl,
                        const float* __restrict__ bias, float* __restrict__ C0, float* __restrict__ C1)
{
    int z = blockIdx.z;
    gemm_core(Ah + z*(FFF/2), Al + z*(FFF/2), FFF,
              Wh + (size_t)(z*(FFF/2))*DD, Wl + (size_t)(z*(FFF/2))*DD, DD,
              bias, z ? C1 : C0, nullptr, nullptr, DD, FFF/2, 0, blockIdx.y*128, blockIdx.x*128, z == 0);
}

// ================= fused flash attention with in-kernel Q@Ginv ================
// smem (bf16 elems): prologue Q0|Q1|G0|G1 ; mainloop reuses as K0|K1|V0|V1
#define SCR 72
#define FQ0 0
#define FQ1 (128*SCR)            // 9216
#define FG0 (2*128*SCR)          // 18432
#define FG1 (FG0 + 64*SCR)       // 23040
#define FK0 0
#define FK1 (64*SCR)             // 4608
#define FV0 (2*64*SCR)           // 9216
#define FV1 (3*64*SCR)           // 13824
#define FL_SMEM ((2*128*SCR + 2*64*SCR)*2)   // 55296 B

__global__ __launch_bounds__(256)
void flash_kernel(const __nv_bfloat16* __restrict__ qh, const __nv_bfloat16* __restrict__ ql,
                  const __nv_bfloat16* __restrict__ kh, const __nv_bfloat16* __restrict__ kl,
                  const __nv_bfloat16* __restrict__ vh, const __nv_bfloat16* __restrict__ vl,
                  const float* __restrict__ ginv, float* __restrict__ ctx)
{
    extern __shared__ __nv_bfloat16 fs[];
    const int bh = blockIdx.y, b = bh / NHH, h = bh % NHH;
    const int i0 = blockIdx.x * 128;
    const int tid = threadIdx.x, warp = tid >> 5, lane = tid & 31;
    const int wm = warp * 16;
    const uint32_t sbase = (uint32_t)__cvta_generic_to_shared(fs);

    // stage Q pairs (cp.async)
    #pragma unroll
    for (int it = 0; it < 4; it++) {
        int ch = it*256 + tid, row = ch >> 3, col = (ch & 7) * 8;
        uint32_t d = sbase + (uint32_t)(row*SCR + col)*2;
        size_t gof = (size_t)(b*SS + i0 + row)*DD + h*HDD + col;
        cp16(d,          qh + gof);
        cp16(d + FQ1*2,  ql + gof);
    }
    asm volatile("cp.async.commit_group;" ::: "memory");
    // stage ginv hi/lo (symmetric => row-major works as K-major B operand)
    {
        const float* gb = ginv + b * (HDD*HDD);
        #pragma unroll
        for (int it = 0; it < 8; it++) {
            int idx = it*512 + tid*2;
            int row = idx >> 6, col = idx & 63;
            float2 gv = *(const float2*)&gb[idx];
            uint32_t lo, hi = packpair(gv.x, gv.y, lo);
            *(uint32_t*)&fs[FG0 + row*SCR + col] = hi;
            *(uint32_t*)&fs[FG1 + row*SCR + col] = lo;
        }
    }
    asm volatile("cp.async.wait_group 0;" ::: "memory");
    __syncthreads();

    // QG = Q @ Ginv  (bf16x3; scores-style non-trans B mapping)
    float qga[8][4] = {};
    #pragma unroll
    for (int ks = 0; ks < 4; ks++) {
        uint32_t aoff = (uint32_t)(((wm + (lane&15))*SCR + ks*16 + ((lane>>4)<<3))*2);
        uint32_t a0[4], a1[4];
        ldsm_x4(a0[0],a0[1],a0[2],a0[3], sbase + FQ0*2 + aoff);
        ldsm_x4(a1[0],a1[1],a1[2],a1[3], sbase + FQ1*2 + aoff);
        #pragma unroll
        for (int jt = 0; jt < 4; jt++) {
            uint32_t boff = (uint32_t)(((jt*16 + (lane&15))*SCR + ks*16 + ((lane>>4)<<3))*2);
            uint32_t r0,r1,r2,r3;
            uint32_t bh0[2], bh1[2], bl0[2], bl1[2];
            ldsm_x4(r0,r1,r2,r3, sbase + FG0*2 + boff);
            bh0[0]=r0; bh0[1]=r2; bh1[0]=r1; bh1[1]=r3;
            ldsm_x4(r0,r1,r2,r3, sbase + FG1*2 + boff);
            bl0[0]=r0; bl0[1]=r2; bl1[0]=r1; bl1[1]=r3;
            mma_bf16(qga[jt*2],   a0, bh0); mma_bf16(qga[jt*2],   a0, bl0); mma_bf16(qga[jt*2],   a1, bh0);
            mma_bf16(qga[jt*2+1], a0, bh1); mma_bf16(qga[jt*2+1], a0, bl1); mma_bf16(qga[jt*2+1], a1, bh1);
        }
    }
    // repack QG C-frags -> A-frags (hi + residual lo), per k16 block
    uint32_t qa_h[4][4], qa_l[4][4];
    #pragma unroll
    for (int eks = 0; eks < 4; eks++) {
        qa_h[eks][0] = packpair(qga[2*eks][0],   qga[2*eks][1],   qa_l[eks][0]);
        qa_h[eks][1] = packpair(qga[2*eks][2],   qga[2*eks][3],   qa_l[eks][1]);
        qa_h[eks][2] = packpair(qga[2*eks+1][0], qga[2*eks+1][1], qa_l[eks][2]);
        qa_h[eks][3] = packpair(qga[2*eks+1][2], qga[2*eks+1][3], qa_l[eks][3]);
    }

    float m0 = -1e30f, m1 = -1e30f, l0 = 0.f, l1 = 0.f;
    float acc[8][4] = {};

    for (int j0 = 0; j0 < SS; j0 += 64) {
        __syncthreads();   // smem free (QG done / previous tile consumed)
        #pragma unroll
        for (int it = 0; it < 2; it++) {
            int ch = it*256 + tid, row = ch >> 3, col = (ch & 7) * 8;
            uint32_t d = sbase + (uint32_t)(row*SCR + col)*2;
            size_t gof = (size_t)(b*SS + j0 + row)*DD + h*HDD + col;
            cp16(d + FK0*2, kh + gof);
            cp16(d + FK1*2, kl + gof);
            cp16(d + FV0*2, vh + gof);
            cp16(d + FV1*2, vl + gof);
        }
        asm volatile("cp.async.commit_group;" ::: "memory");
        asm volatile("cp.async.wait_group 0;" ::: "memory");
        __syncthreads();

        float s[8][4] = {};
        #pragma unroll
        for (int ks = 0; ks < 4; ks++) {
            #pragma unroll
            for (int jt = 0; jt < 4; jt++) {
                uint32_t boff = (uint32_t)(((jt*16 + (lane&15))*SCR + ks*16 + ((lane>>4)<<3))*2);
                uint32_t r0,r1,r2,r3;
                uint32_t bh0[2], bh1[2], bl0[2], bl1[2];
                ldsm_x4(r0,r1,r2,r3, sbase + FK0*2 + boff);
                bh0[0]=r0; bh0[1]=r2; bh1[0]=r1; bh1[1]=r3;
                ldsm_x4(r0,r1,r2,r3, sbase + FK1*2 + boff);
                bl0[0]=r0; bl0[1]=r2; bl1[0]=r1; bl1[1]=r3;
                mma_bf16(s[jt*2],   qa_h[ks], bh0); mma_bf16(s[jt*2],   qa_h[ks], bl0); mma_bf16(s[jt*2],   qa_l[ks], bh0);
                mma_bf16(s[jt*2+1], qa_h[ks], bh1); mma_bf16(s[jt*2+1], qa_h[ks], bl1); mma_bf16(s[jt*2+1], qa_l[ks], bh1);
            }
        }
        float mt0 = -1e30f, mt1 = -1e30f;
        #pragma unroll
        for (int n = 0; n < 8; n++) {
            s[n][0] *= 0.125f; s[n][1] *= 0.125f; s[n][2] *= 0.125f; s[n][3] *= 0.125f;
            mt0 = fmaxf(mt0, fmaxf(s[n][0], s[n][1]));
            mt1 = fmaxf(mt1, fmaxf(s[n][2], s[n][3]));
        }
        #pragma unroll
        for (int o = 1; o < 4; o <<= 1) {
            mt0 = fmaxf(mt0, __shfl_xor_sync(~0u, mt0, o));
            mt1 = fmaxf(mt1, __shfl_xor_sync(~0u, mt1, o));
        }
        float mn0 = fmaxf(m0, mt0), mn1 = fmaxf(m1, mt1);
        float al0 = expf(m0 - mn0), al1 = expf(m1 - mn1);
        float sum0 = 0.f, sum1 = 0.f;
        #pragma unroll
        for (int n = 0; n < 8; n++) {
            s[n][0] = expf(s[n][0]-mn0); s[n][1] = expf(s[n][1]-mn0);
            s[n][2] = expf(s[n][2]-mn1); s[n][3] = expf(s[n][3]-mn1);
            sum0 += s[n][0] + s[n][1]; sum1 += s[n][2] + s[n][3];
        }
        #pragma unroll
        for (int o = 1; o < 4; o <<= 1) {
            sum0 += __shfl_xor_sync(~0u, sum0, o);
            sum1 += __shfl_xor_sync(~0u, sum1, o);
        }
        m0 = mn0; m1 = mn1;
        l0 = l0*al0 + sum0; l1 = l1*al1 + sum1;
        #pragma unroll
        for (int n = 0; n < 8; n++) {
            acc[n][0] *= al0; acc[n][1] *= al0; acc[n][2] *= al1; acc[n][3] *= al1;
        }
        #pragma unroll
        for (int ks = 0; ks < 4; ks++) {
            uint32_t ph[4], pl[4];
            ph[0] = packpair(s[2*ks][0],   s[2*ks][1],   pl[0]);
            ph[1] = packpair(s[2*ks][2],   s[2*ks][3],   pl[1]);
            ph[2] = packpair(s[2*ks+1][0], s[2*ks+1][1], pl[2]);
            ph[3] = packpair(s[2*ks+1][2], s[2*ks+1][3], pl[3]);
            #pragma unroll
            for (int jt = 0; jt < 4; jt++) {
                uint32_t boff = (uint32_t)(((ks*16 + (lane&15))*SCR + jt*16 + ((lane>>4)<<3))*2);
                uint32_t r0,r1,r2,r3;
                uint32_t bh0[2], bh1[2], bl0[2], bl1[2];
                ldsm_x4_t(r0,r1,r2,r3, sbase + FV0*2 + boff);
                bh0[0]=r0; bh0[1]=r1; bh1[0]=r2; bh1[1]=r3;
                ldsm_x4_t(r0,r1,r2,r3, sbase + FV1*2 + boff);
                bl0[0]=r0; bl0[1]=r1; bl1[0]=r2; bl1[1]=r3;
                mma_bf16(acc[jt*2],   ph, bh0); mma_bf16(acc[jt*2],   ph, bl0); mma_bf16(acc[jt*2],   pl, bh0);
                mma_bf16(acc[jt*2+1], ph, bh1); mma_bf16(acc[jt*2+1], ph, bl1); mma_bf16(acc[jt*2+1], pl, bh1);
            }
        }
    }
    float il0 = 1.f / l0, il1 = 1.f / l1;
    int r0 = i0 + wm + (lane >> 2);
    #pragma unroll
    for (int n = 0; n < 8; n++) {
        int c0 = h*HDD + n*8 + (lane&3)*2;
        *(float2*)&ctx[(size_t)(b*SS + r0)*DD + c0]   = make_float2(acc[n][0]*il0, acc[n][1]*il0);
        *(float2*)&ctx[(size_t)(b*SS + r0+8)*DD + c0] = make_float2(acc[n][2]*il1, acc[n][3]*il1);
    }
}

// ---- LayerNorm family ----
#define LN_BODY(EXPR) \
    int t = blockIdx.x, tid = threadIdx.x; \
    __shared__ float red[256]; \
    size_t base = (size_t)t * DD; \
    float v[3]; float sum = 0.f; \
    _Pragma("unroll") for (int i = 0; i < 3; i++) { int d = tid + i*256; v[i] = (EXPR); sum += v[i]; } \
    red[tid] = sum; __syncthreads(); \
    for (int o = 128; o > 0; o >>= 1) { if (tid < o) red[tid] += red[tid+o]; __syncthreads(); } \
    float mean = red[0] * (1.0f/DD); __syncthreads(); \
    float vs = 0.f; \
    _Pragma("unroll") for (int i = 0; i < 3; i++) { float d0 = v[i]-mean; vs += d0*d0; } \
    red[tid] = vs; __syncthreads(); \
    for (int o = 128; o > 0; o >>= 1) { if (tid < o) red[tid] += red[tid+o]; __syncthreads(); } \
    float rstd = rsqrtf(red[0]*(1.0f/DD) + 1e-12f); \
    _Pragma("unroll") for (int i = 0; i < 3; i++) { int d = tid + i*256; \
        float vv = (v[i]-mean)*rstd*w[d] + bb[d]; out[base+d] = vv; \
        if (oh) { __nv_bfloat16 hb = __float2bfloat16(vv); oh[base+d] = hb; \
                  ol[base+d] = __float2bfloat16(vv - __bfloat162float(hb)); } }

__global__ __launch_bounds__(256)
void embed_ln_kernel(const int* __restrict__ ids, const int* __restrict__ tts,
                     const float* __restrict__ we, const float* __restrict__ pe, const float* __restrict__ te,
                     const float* __restrict__ w, const float* __restrict__ bb, float* __restrict__ out,
                     __nv_bfloat16* __restrict__ oh, __nv_bfloat16* __restrict__ ol)
{
    int s = blockIdx.x % SS;
    const float* wr = we + (size_t)ids[blockIdx.x] * DD;
    const float* pr = pe + (size_t)s * DD;
    const float* tr = te + (size_t)tts[blockIdx.x] * DD;
    LN_BODY(wr[d] + pr[d] + tr[d])
}
__global__ __launch_bounds__(256)
void add_ln_kernel(const float* __restrict__ x, const float* __restrict__ y,
                   const float* __restrict__ w, const float* __restrict__ bb, float* __restrict__ out,
                   __nv_bfloat16* __restrict__ oh, __nv_bfloat16* __restrict__ ol)
{ LN_BODY(x[base+d] + y[base+d]) }
__global__ __launch_bounds__(256)
void add_ln3_kernel(const float* __restrict__ x1, const float* __restrict__ x2, const float* __restrict__ y,
                    const float* __restrict__ w, const float* __restrict__ bb, float* __restrict__ out,
                    __nv_bfloat16* __restrict__ oh, __nv_bfloat16* __restrict__ ol)
{ LN_BODY(x1[base+d] + x2[base+d] + y[base+d]) }

// ---- metric path ----
__global__ __launch_bounds__(256)
void pool_kernel(const float* __restrict__ h, float* __restrict__ hmean)
{
    int b = blockIdx.x, c0 = blockIdx.y * 128, tid = threadIdx.x;
    int col = c0 + (tid & 127), rg = tid >> 7;
    __shared__ float part[256];
    float s = 0.f;
    for (int t = rg*256; t < rg*256 + 256; t++) s += h[((size_t)b*SS + t)*DD + col];
    part[tid] = s; __syncthreads();
    if (tid < 128) hmean[b*DD + col] = (part[tid] + part[tid+128]) * (1.0f/SS);
}
__global__ __launch_bounds__(256)
void cw_kernel(const float* __restrict__ hmean, const float* __restrict__ Wcp,
               const float* __restrict__ bcp, float* __restrict__ cw)
{
    int b = blockIdx.x, tid = threadIdx.x;
    __shared__ float hm[DD]; __shared__ float part[256];
    for (int i = tid; i < DD; i += 256) hm[i] = hmean[b*DD + i];
    __syncthreads();
    int j = tid & 63, d0 = (tid >> 6) * 192;
    float acc = 0.f;
    #pragma unroll 4
    for (int d = d0; d < d0 + 192; d++) acc = fmaf(hm[d], Wcp[(size_t)d*DD + j], acc);
    part[tid] = acc; __syncthreads();
    if (tid < 64) {
        float y = bcp[tid] + part[tid] + part[tid+64] + part[tid+128] + part[tid+192];
        cw[b*HDD + tid] = 1.f / (1.f + expf(-y));
    }
}
__global__ __launch_bounds__(256)
void ginv_kernel(const float* __restrict__ Lm_l, const float* __restrict__ diag_l,
                 const float* __restrict__ cw, float* __restrict__ ginv)
{
    int b = blockIdx.x, tid = threadIdx.x;
    __shared__ float L[64][64]; __shared__ float A[64][65]; __shared__ float fcol[64];
    for (int it = 0; it < 16; it++) { int idx = it*256+tid; L[idx>>6][idx&63] = Lm_l[idx] * cw[b*HDD + (idx>>6)]; }
    __syncthreads();
    for (int it = 0; it < 16; it++) {
        int idx = it*256+tid, i = idx>>6, j = idx&63;
        float s = 0.f;
        for (int t2 = 0; t2 < 64; t2++) s = fmaf(L[i][t2], L[j][t2], s);
        if (i == j) s += diag_l[i] + 1e-6f + 0.1f;
        A[i][j] = s;
    }
    __syncthreads();
    for (int it = 0; it < 16; it++) { int idx = it*256+tid; L[idx>>6][idx&63] = ((idx>>6)==(idx&63)) ? 1.f : 0.f; }
    __syncthreads();
    for (int p = 0; p < 64; p++) {
        float ip = 1.f / A[p][p];
        float myf = (tid < 64) ? A[tid][p] : 0.f;
        __syncthreads();
        if (tid < 64) A[p][tid] *= ip; else if (tid < 128) L[p][tid-64] *= ip;
        if (tid < 64) fcol[tid] = (tid == p) ? 0.f : myf;
        __syncthreads();
        for (int it = 0; it < 32; it++) {
            int idx = it*256+tid, r = idx>>7, c = idx&127;
            if (r != p) { if (c < 64) A[r][c] -= fcol[r]*A[p][c]; else L[r][c-64] -= fcol[r]*L[p][c-64]; }
        }
        __syncthreads();
    }
    for (int it = 0; it < 16; it++) { int idx = it*256+tid; ginv[b*(HDD*HDD) + idx] = L[idx>>6][idx&63]; }
}

#define SYM(p, s) cudaGetSymbolAddress((void**)&p, s)

extern "C" void kernel_launch(void* const* d_in, const int* in_sizes, int n_in, void* d_out, int out_size)
{
    const int* ids = (const int*)d_in[0];
    const int* tts = (const int*)d_in[1];
    const float* we = (const float*)d_in[2];
    const float* pe = (const float*)d_in[3];
    const float* te = (const float*)d_in[4];
    const float* lnew = (const float*)d_in[5];
    const float* lneb = (const float*)d_in[6];
    const float* Wq = (const float*)d_in[7];
    const float* bq = (const float*)d_in[8];
    const float* Wk = (const float*)d_in[9];
    const float* bk = (const float*)d_in[10];
    const float* Wv = (const float*)d_in[11];
    const float* bv = (const float*)d_in[12];
    const float* Lm = (const float*)d_in[13];
    const float* dg = (const float*)d_in[14];
    const float* Wcp = (const float*)d_in[15];
    const float* bcp = (const float*)d_in[16];
    const float* Wi = (const float*)d_in[17];
    const float* bi = (const float*)d_in[18];
    const float* Wo = (const float*)d_in[19];
    const float* bo = (const float*)d_in[20];
    const float* l1w = (const float*)d_in[21];
    const float* l1b = (const float*)d_in[22];
    const float* l2w = (const float*)d_in[23];
    const float* l2b = (const float*)d_in[24];

    float *h,*ctx,*a,*f,*o,*o2,*hmean,*cw,*ginv;
    __nv_bfloat16 *wqh,*wql,*wkh,*wkl,*wvh,*wvl,*wih,*wil,*woh,*wol;
    __nv_bfloat16 *hh,*hl,*ah,*al,*fh,*fl,*kh,*kl,*vh,*vl,*qh,*ql;
    SYM(h,g_h); SYM(ctx,g_ctx); SYM(a,g_a); SYM(f,g_f);
    SYM(o,g_o); SYM(o2,g_o2);
    SYM(hmean,g_hmean); SYM(cw,g_cw); SYM(ginv,g_ginv);
    SYM(wqh,g_wq_h); SYM(wql,g_wq_l); SYM(wkh,g_wk_h); SYM(wkl,g_wk_l);
    SYM(wvh,g_wv_h); SYM(wvl,g_wv_l); SYM(wih,g_wi_h); SYM(wil,g_wi_l);
    SYM(woh,g_wo_h); SYM(wol,g_wo_l);
    SYM(hh,g_hh); SYM(hl,g_hl); SYM(ah,g_ah); SYM(al,g_al); SYM(fh,g_fh); SYM(fl,g_fl);
    SYM(kh,g_kh); SYM(kl,g_kl); SYM(vh,g_vh); SYM(vl,g_vl); SYM(qh,g_qh); SYM(ql,g_ql);

    cudaFuncSetAttribute(gemm_kernel,        cudaFuncAttributeMaxDynamicSharedMemorySize, G_SMEM);
    cudaFuncSetAttribute(gemm_qkv_kernel,    cudaFuncAttributeMaxDynamicSharedMemorySize, G_SMEM);
    cudaFuncSetAttribute(gemm_splitk_kernel, cudaFuncAttributeMaxDynamicSharedMemorySize, G_SMEM);
    cudaFuncSetAttribute(flash_kernel,       cudaFuncAttributeMaxDynamicSharedMemorySize, FL_SMEM);

    split_w_kernel<<<1024, 256>>>(Wq, wqh, wql, NLL*DD*DD/4);
    split_w_kernel<<<1024, 256>>>(Wk, wkh, wkl, NLL*DD*DD/4);
    split_w_kernel<<<1024, 256>>>(Wv, wvh, wvl, NLL*DD*DD/4);
    split_w_kernel<<<2048, 256>>>(Wi, wih, wil, NLL*DD*FFF/4);
    split_w_kernel<<<2048, 256>>>(Wo, woh, wol, NLL*FFF*DD/4);

    embed_ln_kernel<<<MT, 256>>>(ids, tts, we, pe, te, lnew, lneb, h, hh, hl);

    for (int l = 0; l < NLL; l++) {
        size_t od = (size_t)l*DD*DD, of = (size_t)l*DD*FFF;

        gemm_qkv_kernel<<<dim3(18, 32), 256, G_SMEM>>>(hh, hl, wqh+od, wql+od, wkh+od, wkl+od,
            wvh+od, wvl+od, bq + l*DD, bk + l*DD, bv + l*DD, qh, ql, kh, kl, vh, vl);

        pool_kernel<<<dim3(BB, 6), 256>>>(h, hmean);
        cw_kernel<<<BB, 256>>>(hmean, Wcp + od, bcp + l*DD, cw);
        ginv_kernel<<<BB, 256>>>(Lm + (size_t)l*DD*64, dg + l*DD, cw, ginv);

        flash_kernel<<<dim3(SS/128, BB*NHH), 256, FL_SMEM>>>(qh, ql, kh, kl, vh, vl, ginv, ctx);

        add_ln_kernel<<<MT, 256>>>(ctx, h, l1w + l*DD, l1b + l*DD, a, ah, al);

        gemm_kernel<<<dim3(FFF/128, 32), 256, G_SMEM>>>(ah, al, wih+of, wil+of,
            bi + (size_t)l*FFF, f, fh, fl, FFF, DD, 1);
        gemm_splitk_kernel<<<dim3(DD/128, 32, 2), 256, G_SMEM>>>(fh, fl, woh+of, wol+of,
            bo + l*DD, o, o2);

        float* out_h = (l == NLL-1) ? (float*)d_out : h;
        add_ln3_kernel<<<MT, 256>>>(o, o2, a, l2w + l*DD, l2b + l*DD, out_h,
                                    (l == NLL-1) ? nullptr : hh, (l == NLL-1) ? nullptr : hl);
    }
}

// round 17
// speedup vs baseline: 1.0344x; 1.0221x over previous
#include <cuda_runtime.h>
#include <cuda_bf16.h>
#include <stdint.h>
#include <math.h>

#define BB 8
#define SS 512
#define DD 768
#define NHH 12
#define HDD 64
#define FFF 3072
#define NLL 12
#define MT (BB*SS)

__device__ float g_h[MT*DD];
__device__ float g_ctx[MT*DD];
__device__ float g_a[MT*DD];
__device__ float g_o[MT*DD];
__device__ float g_o2[MT*DD];
__device__ float g_hmean[BB*DD];
__device__ float g_ginv[BB*HDD*HDD];
__device__ __nv_bfloat16 g_wq_h[NLL*DD*DD], g_wq_l[NLL*DD*DD];
__device__ __nv_bfloat16 g_wk_h[NLL*DD*DD], g_wk_l[NLL*DD*DD];
__device__ __nv_bfloat16 g_wv_h[NLL*DD*DD], g_wv_l[NLL*DD*DD];
__device__ __nv_bfloat16 g_wi_h[(size_t)NLL*DD*FFF], g_wi_l[(size_t)NLL*DD*FFF];
__device__ __nv_bfloat16 g_wo_h[(size_t)NLL*FFF*DD], g_wo_l[(size_t)NLL*FFF*DD];
__device__ __nv_bfloat16 g_hh[MT*DD], g_hl[MT*DD];
__device__ __nv_bfloat16 g_ah[MT*DD], g_al[MT*DD];
__device__ __nv_bfloat16 g_fh[MT*FFF], g_fl[MT*FFF];
__device__ __nv_bfloat16 g_kh[MT*DD], g_kl[MT*DD];
__device__ __nv_bfloat16 g_vh[MT*DD], g_vl[MT*DD];
__device__ __nv_bfloat16 g_qh[MT*DD], g_ql[MT*DD];

__device__ __forceinline__ void ldsm_x4(uint32_t& r0, uint32_t& r1, uint32_t& r2, uint32_t& r3, uint32_t a)
{ asm volatile("ldmatrix.sync.aligned.m8n8.x4.shared.b16 {%0,%1,%2,%3},[%4];" : "=r"(r0),"=r"(r1),"=r"(r2),"=r"(r3) : "r"(a)); }
__device__ __forceinline__ void ldsm_x4_t(uint32_t& r0, uint32_t& r1, uint32_t& r2, uint32_t& r3, uint32_t a)
{ asm volatile("ldmatrix.sync.aligned.m8n8.x4.trans.shared.b16 {%0,%1,%2,%3},[%4];" : "=r"(r0),"=r"(r1),"=r"(r2),"=r"(r3) : "r"(a)); }
__device__ __forceinline__ void mma_bf16(float* c, const uint32_t* a, const uint32_t* b)
{ asm volatile("mma.sync.aligned.m16n8k16.row.col.f32.bf16.bf16.f32 {%0,%1,%2,%3},{%4,%5,%6,%7},{%8,%9},{%0,%1,%2,%3};"
               : "+f"(c[0]),"+f"(c[1]),"+f"(c[2]),"+f"(c[3])
               : "r"(a[0]),"r"(a[1]),"r"(a[2]),"r"(a[3]),"r"(b[0]),"r"(b[1])); }
__device__ __forceinline__ float gelu(float x) { return 0.5f*x*(1.f+erff(x*0.70710678118654752f)); }
__device__ __forceinline__ uint32_t packpair(float x, float y, uint32_t& lo)
{
    __nv_bfloat162 h = __floats2bfloat162_rn(x, y);
    __nv_bfloat162 l = __floats2bfloat162_rn(x-__low2float(h), y-__high2float(h));
    lo = *(uint32_t*)&l; return *(uint32_t*)&h;
}
__device__ __forceinline__ void cp16(uint32_t s, const void* g)
{ asm volatile("cp.async.cg.shared.global [%0],[%1],16;" :: "r"(s),"l"(g) : "memory"); }

__global__ __launch_bounds__(256)
void split_w_kernel(const float* __restrict__ src, __nv_bfloat16* __restrict__ dh,
                    __nv_bfloat16* __restrict__ dl, int n4)
{
    for (int i = blockIdx.x*256 + threadIdx.x; i < n4; i += gridDim.x*256) {
        float4 v = ((const float4*)src)[i];
        uint32_t l0, h0 = packpair(v.x, v.y, l0);
        uint32_t l1, h1 = packpair(v.z, v.w, l1);
        ((uint32_t*)dh)[i*2] = h0; ((uint32_t*)dh)[i*2+1] = h1;
        ((uint32_t*)dl)[i*2] = l0; ((uint32_t*)dl)[i*2+1] = l1;
    }
}

// ================= GEMM core (unchanged) ================
#define GRA 40
#define GRB 136
#define GASZ (128*GRA)
#define GBSZ (32*GRB)
#define GSTG_B ((2*GASZ + 2*GBSZ)*2)
#define G_SMEM (2*GSTG_B)

__device__ __forceinline__ void gemm_core(
    const __nv_bfloat16* Ah, const __nv_bfloat16* Al, int lda,
    const __nv_bfloat16* Wh, const __nv_bfloat16* Wl, int ldw,
    const float* bias, float* C, __nv_bfloat16* Ch, __nv_bfloat16* Cl, int ldc,
    int K, int act, int bm, int bn, int addb)
{
    extern __shared__ char smem[];
    const int tid = threadIdx.x, warp = tid >> 5, lane = tid & 31;
    const int wm = (warp & 3) * 32, wn = (warp >> 2) * 64;
    const uint32_t sb = (uint32_t)__cvta_generic_to_shared(smem);
    const int KT = K >> 5;
    float acc[2][8][4] = {};

    #define ISSUE(buf, k0) do { \
        uint32_t st = sb + (uint32_t)(buf)*GSTG_B; \
        _Pragma("unroll") for (int kk = 0; kk < 2; kk++) { \
            int ch = tid + kk*256; \
            int r = ch >> 2, o = (ch & 3) * 8; \
            uint32_t d = st + (uint32_t)(r*GRA + o)*2; \
            cp16(d,          Ah + (size_t)(bm+r)*lda + (k0) + o); \
            cp16(d + GASZ*2, Al + (size_t)(bm+r)*lda + (k0) + o); \
            int r2 = ch >> 4, o2 = (ch & 15) * 8; \
            uint32_t d2 = st + (uint32_t)(2*GASZ + r2*GRB + o2)*2; \
            cp16(d2,          Wh + (size_t)((k0)+r2)*ldw + bn + o2); \
            cp16(d2 + GBSZ*2, Wl + (size_t)((k0)+r2)*ldw + bn + o2); \
        } \
        asm volatile("cp.async.commit_group;" ::: "memory"); \
    } while(0)

    ISSUE(0, 0);
    for (int t = 0; t < KT; t++) {
        if (t + 1 < KT) { ISSUE((t+1)&1, (t+1)*32); asm volatile("cp.async.wait_group 1;" ::: "memory"); }
        else            { asm volatile("cp.async.wait_group 0;" ::: "memory"); }
        __syncthreads();
        uint32_t base = sb + (uint32_t)(t & 1) * GSTG_B;
        uint32_t a0b = base, a1b = base + GASZ*2, b0b = base + 2*GASZ*2, b1b = base + (2*GASZ+GBSZ)*2;
        #pragma unroll
        for (int ks = 0; ks < 2; ks++) {
            uint32_t a0[2][4], a1[2][4];
            #pragma unroll
            for (int i = 0; i < 2; i++) {
                uint32_t off = (uint32_t)(((wm + i*16 + (lane&15))*GRA + ks*16 + ((lane>>4)<<3))*2);
                ldsm_x4(a0[i][0],a0[i][1],a0[i][2],a0[i][3], a0b+off);
                ldsm_x4(a1[i][0],a1[i][1],a1[i][2],a1[i][3], a1b+off);
            }
            #pragma unroll
            for (int j = 0; j < 4; j++) {
                uint32_t boff = (uint32_t)(((ks*16 + (lane&15))*GRB + wn + j*16 + ((lane>>4)<<3))*2);
                uint32_t h0,h1,h2,h3, l0,l1,l2,l3;
                ldsm_x4_t(h0,h1,h2,h3, b0b+boff);
                ldsm_x4_t(l0,l1,l2,l3, b1b+boff);
                uint32_t bh0[2]={h0,h1}, bh1[2]={h2,h3}, bl0[2]={l0,l1}, bl1[2]={l2,l3};
                #pragma unroll
                for (int i = 0; i < 2; i++) {
                    mma_bf16(acc[i][j*2],   a0[i], bh0); mma_bf16(acc[i][j*2],   a0[i], bl0); mma_bf16(acc[i][j*2],   a1[i], bh0);
                    mma_bf16(acc[i][j*2+1], a0[i], bh1); mma_bf16(acc[i][j*2+1], a0[i], bl1); mma_bf16(acc[i][j*2+1], a1[i], bh1);
                }
            }
        }
        __syncthreads();
    }
    #undef ISSUE

    #pragma unroll
    for (int i = 0; i < 2; i++) {
        int r0 = bm + wm + i*16 + (lane >> 2);
        #pragma unroll
        for (int j = 0; j < 8; j++) {
            int c0 = bn + wn + j*8 + (lane & 3)*2;
            float b0v = addb ? bias[c0] : 0.f, b1v = addb ? bias[c0+1] : 0.f;
            float v0 = acc[i][j][0]+b0v, v1 = acc[i][j][1]+b1v;
            float v2 = acc[i][j][2]+b0v, v3 = acc[i][j][3]+b1v;
            if (act) { v0 = gelu(v0); v1 = gelu(v1); v2 = gelu(v2); v3 = gelu(v3); }
            if (C) {
                *(float2*)&C[(size_t)r0*ldc + c0]     = make_float2(v0, v1);
                *(float2*)&C[(size_t)(r0+8)*ldc + c0] = make_float2(v2, v3);
            }
            if (Ch) {
                uint32_t lo, hi = packpair(v0, v1, lo);
                *(uint32_t*)&Ch[(size_t)r0*ldc + c0] = hi; *(uint32_t*)&Cl[(size_t)r0*ldc + c0] = lo;
                hi = packpair(v2, v3, lo);
                *(uint32_t*)&Ch[(size_t)(r0+8)*ldc + c0] = hi; *(uint32_t*)&Cl[(size_t)(r0+8)*ldc + c0] = lo;
            }
        }
    }
}

__global__ __launch_bounds__(256, 2)
void gemm_kernel(const __nv_bfloat16* __restrict__ Ah, const __nv_bfloat16* __restrict__ Al,
                 const __nv_bfloat16* __restrict__ Wh, const __nv_bfloat16* __restrict__ Wl,
                 const float* __restrict__ bias, float* __restrict__ C,
                 __nv_bfloat16* __restrict__ Ch, __nv_bfloat16* __restrict__ Cl, int N, int K, int act)
{ gemm_core(Ah, Al, K, Wh, Wl, N, bias, C, Ch, Cl, N, K, act, blockIdx.y*128, blockIdx.x*128, 1); }

__global__ __launch_bounds__(256, 2)
void gemm_qkv_kernel(const __nv_bfloat16* __restrict__ Ah, const __nv_bfloat16* __restrict__ Al,
                     const __nv_bfloat16* Wqh, const __nv_bfloat16* Wql,
                     const __nv_bfloat16* Wkh, const __nv_bfloat16* Wkl,
                     const __nv_bfloat16* Wvh, const __nv_bfloat16* Wvl,
                     const float* b0, const float* b1, const float* b2,
                     __nv_bfloat16* qh, __nv_bfloat16* ql,
                     __nv_bfloat16* kh, __nv_bfloat16* kl,
                     __nv_bfloat16* vh, __nv_bfloat16* vl)
{
    int sel = blockIdx.x / 6, bn = (blockIdx.x % 6) * 128;
    const __nv_bfloat16* Wh = sel==0?Wqh:sel==1?Wkh:Wvh;
    const __nv_bfloat16* Wl = sel==0?Wql:sel==1?Wkl:Wvl;
    const float* bias = sel==0?b0:sel==1?b1:b2;
    __nv_bfloat16* Ch = sel==0?qh:sel==1?kh:vh;
    __nv_bfloat16* Cl = sel==0?ql:sel==1?kl:vl;
    gemm_core(Ah, Al, DD, Wh, Wl, DD, bias, nullptr, Ch, Cl, DD, DD, 0, blockIdx.y*128, bn, 1);
}

__global__ __launch_bounds__(256, 2)
void gemm_splitk_kernel(const __nv_bfloat16* __restrict__ Ah, const __nv_bfloat16* __restrict__ Al,
                        const __nv_bfloat16* __restrict__ Wh, const __nv_bfloat16* __restrict__ Wl,
                        const float* __restrict__ bias, float* __restrict__ C0, float* __restrict__ C1)
{
    int z = blockIdx.z;
    gemm_core(Ah + z*(FFF/2), Al + z*(FFF/2), FFF,
              Wh + (size_t)(z*(FFF/2))*DD, Wl + (size_t)(z*(FFF/2))*DD, DD,
              bias, z ? C1 : C0, nullptr, nullptr, DD, FFF/2, 0, blockIdx.y*128, blockIdx.x*128, z == 0);
}

// ================= fused flash attention with in-kernel Q@Ginv (unchanged from R15) ================
#define SCR 72
#define FQ0 0
#define FQ1 (128*SCR)
#define FG0 (2*128*SCR)
#define FG1 (FG0 + 64*SCR)
#define FK0 0
#define FK1 (64*SCR)
#define FV0 (2*64*SCR)
#define FV1 (3*64*SCR)
#define FL_SMEM ((2*128*SCR + 2*64*SCR)*2)

__global__ __launch_bounds__(256)
void flash_kernel(const __nv_bfloat16* __restrict__ qh, const __nv_bfloat16* __restrict__ ql,
                  const __nv_bfloat16* __restrict__ kh, const __nv_bfloat16* __restrict__ kl,
                  const __nv_bfloat16* __restrict__ vh, const __nv_bfloat16* __restrict__ vl,
                  const float* __restrict__ ginv, float* __restrict__ ctx)
{
    extern __shared__ __nv_bfloat16 fs[];
    const int bh = blockIdx.y, b = bh / NHH, h = bh % NHH;
    const int i0 = blockIdx.x * 128;
    const int tid = threadIdx.x, warp = tid >> 5, lane = tid & 31;
    const int wm = warp * 16;
    const uint32_t sbase = (uint32_t)__cvta_generic_to_shared(fs);

    #pragma unroll
    for (int it = 0; it < 4; it++) {
        int ch = it*256 + tid, row = ch >> 3, col = (ch & 7) * 8;
        uint32_t d = sbase + (uint32_t)(row*SCR + col)*2;
        size_t gof = (size_t)(b*SS + i0 + row)*DD + h*HDD + col;
        cp16(d,          qh + gof);
        cp16(d + FQ1*2,  ql + gof);
    }
    asm volatile("cp.async.commit_group;" ::: "memory");
    {
        const float* gb = ginv + b * (HDD*HDD);
        #pragma unroll
        for (int it = 0; it < 8; it++) {
            int idx = it*512 + tid*2;
            int row = idx >> 6, col = idx & 63;
            float2 gv = *(const float2*)&gb[idx];
            uint32_t lo, hi = packpair(gv.x, gv.y, lo);
            *(uint32_t*)&fs[FG0 + row*SCR + col] = hi;
            *(uint32_t*)&fs[FG1 + row*SCR + col] = lo;
        }
    }
    asm volatile("cp.async.wait_group 0;" ::: "memory");
    __syncthreads();

    float qga[8][4] = {};
    #pragma unroll
    for (int ks = 0; ks < 4; ks++) {
        uint32_t aoff = (uint32_t)(((wm + (lane&15))*SCR + ks*16 + ((lane>>4)<<3))*2);
        uint32_t a0[4], a1[4];
        ldsm_x4(a0[0],a0[1],a0[2],a0[3], sbase + FQ0*2 + aoff);
        ldsm_x4(a1[0],a1[1],a1[2],a1[3], sbase + FQ1*2 + aoff);
        #pragma unroll
        for (int jt = 0; jt < 4; jt++) {
            uint32_t boff = (uint32_t)(((jt*16 + (lane&15))*SCR + ks*16 + ((lane>>4)<<3))*2);
            uint32_t r0,r1,r2,r3;
            uint32_t bh0[2], bh1[2], bl0[2], bl1[2];
            ldsm_x4(r0,r1,r2,r3, sbase + FG0*2 + boff);
            bh0[0]=r0; bh0[1]=r2; bh1[0]=r1; bh1[1]=r3;
            ldsm_x4(r0,r1,r2,r3, sbase + FG1*2 + boff);
            bl0[0]=r0; bl0[1]=r2; bl1[0]=r1; bl1[1]=r3;
            mma_bf16(qga[jt*2],   a0, bh0); mma_bf16(qga[jt*2],   a0, bl0); mma_bf16(qga[jt*2],   a1, bh0);
            mma_bf16(qga[jt*2+1], a0, bh1); mma_bf16(qga[jt*2+1], a0, bl1); mma_bf16(qga[jt*2+1], a1, bh1);
        }
    }
    uint32_t qa_h[4][4], qa_l[4][4];
    #pragma unroll
    for (int eks = 0; eks < 4; eks++) {
        qa_h[eks][0] = packpair(qga[2*eks][0],   qga[2*eks][1],   qa_l[eks][0]);
        qa_h[eks][1] = packpair(qga[2*eks][2],   qga[2*eks][3],   qa_l[eks][1]);
        qa_h[eks][2] = packpair(qga[2*eks+1][0], qga[2*eks+1][1], qa_l[eks][2]);
        qa_h[eks][3] = packpair(qga[2*eks+1][2], qga[2*eks+1][3], qa_l[eks][3]);
    }

    float m0 = -1e30f, m1 = -1e30f, l0 = 0.f, l1 = 0.f;
    float acc[8][4] = {};

    for (int j0 = 0; j0 < SS; j0 += 64) {
        __syncthreads();
        #pragma unroll
        for (int it = 0; it < 2; it++) {
            int ch = it*256 + tid, row = ch >> 3, col = (ch & 7) * 8;
            uint32_t d = sbase + (uint32_t)(row*SCR + col)*2;
            size_t gof = (size_t)(b*SS + j0 + row)*DD + h*HDD + col;
            cp16(d + FK0*2, kh + gof);
            cp16(d + FK1*2, kl + gof);
            cp16(d + FV0*2, vh + gof);
            cp16(d + FV1*2, vl + gof);
        }
        asm volatile("cp.async.commit_group;" ::: "memory");
        asm volatile("cp.async.wait_group 0;" ::: "memory");
        __syncthreads();

        float s[8][4] = {};
        #pragma unroll
        for (int ks = 0; ks < 4; ks++) {
            #pragma unroll
            for (int jt = 0; jt < 4; jt++) {
                uint32_t boff = (uint32_t)(((jt*16 + (lane&15))*SCR + ks*16 + ((lane>>4)<<3))*2);
                uint32_t r0,r1,r2,r3;
                uint32_t bh0[2], bh1[2], bl0[2], bl1[2];
                ldsm_x4(r0,r1,r2,r3, sbase + FK0*2 + boff);
                bh0[0]=r0; bh0[1]=r2; bh1[0]=r1; bh1[1]=r3;
                ldsm_x4(r0,r1,r2,r3, sbase + FK1*2 + boff);
                bl0[0]=r0; bl0[1]=r2; bl1[0]=r1; bl1[1]=r3;
                mma_bf16(s[jt*2],   qa_h[ks], bh0); mma_bf16(s[jt*2],   qa_h[ks], bl0); mma_bf16(s[jt*2],   qa_l[ks], bh0);
                mma_bf16(s[jt*2+1], qa_h[ks], bh1); mma_bf16(s[jt*2+1], qa_h[ks], bl1); mma_bf16(s[jt*2+1], qa_l[ks], bh1);
            }
        }
        float mt0 = -1e30f, mt1 = -1e30f;
        #pragma unroll
        for (int n = 0; n < 8; n++) {
            s[n][0] *= 0.125f; s[n][1] *= 0.125f; s[n][2] *= 0.125f; s[n][3] *= 0.125f;
            mt0 = fmaxf(mt0, fmaxf(s[n][0], s[n][1]));
            mt1 = fmaxf(mt1, fmaxf(s[n][2], s[n][3]));
        }
        #pragma unroll
        for (int o = 1; o < 4; o <<= 1) {
            mt0 = fmaxf(mt0, __shfl_xor_sync(~0u, mt0, o));
            mt1 = fmaxf(mt1, __shfl_xor_sync(~0u, mt1, o));
        }
        float mn0 = fmaxf(m0, mt0), mn1 = fmaxf(m1, mt1);
        float al0 = expf(m0 - mn0), al1 = expf(m1 - mn1);
        float sum0 = 0.f, sum1 = 0.f;
        #pragma unroll
        for (int n = 0; n < 8; n++) {
            s[n][0] = expf(s[n][0]-mn0); s[n][1] = expf(s[n][1]-mn0);
            s[n][2] = expf(s[n][2]-mn1); s[n][3] = expf(s[n][3]-mn1);
            sum0 += s[n][0] + s[n][1]; sum1 += s[n][2] + s[n][3];
        }
        #pragma unroll
        for (int o = 1; o < 4; o <<= 1) {
            sum0 += __shfl_xor_sync(~0u, sum0, o);
            sum1 += __shfl_xor_sync(~0u, sum1, o);
        }
        m0 = mn0; m1 = mn1;
        l0 = l0*al0 + sum0; l1 = l1*al1 + sum1;
        #pragma unroll
        for (int n = 0; n < 8; n++) {
            acc[n][0] *= al0; acc[n][1] *= al0; acc[n][2] *= al1; acc[n][3] *= al1;
        }
        #pragma unroll
        for (int ks = 0; ks < 4; ks++) {
            uint32_t ph[4], pl[4];
            ph[0] = packpair(s[2*ks][0],   s[2*ks][1],   pl[0]);
            ph[1] = packpair(s[2*ks][2],   s[2*ks][3],   pl[1]);
            ph[2] = packpair(s[2*ks+1][0], s[2*ks+1][1], pl[2]);
            ph[3] = packpair(s[2*ks+1][2], s[2*ks+1][3], pl[3]);
            #pragma unroll
            for (int jt = 0; jt < 4; jt++) {
                uint32_t boff = (uint32_t)(((ks*16 + (lane&15))*SCR + jt*16 + ((lane>>4)<<3))*2);
                uint32_t r0,r1,r2,r3;
                uint32_t bh0[2], bh1[2], bl0[2], bl1[2];
                ldsm_x4_t(r0,r1,r2,r3, sbase + FV0*2 + boff);
                bh0[0]=r0; bh0[1]=r1; bh1[0]=r2; bh1[1]=r3;
                ldsm_x4_t(r0,r1,r2,r3, sbase + FV1*2 + boff);
                bl0[0]=r0; bl0[1]=r1; bl1[0]=r2; bl1[1]=r3;
                mma_bf16(acc[jt*2],   ph, bh0); mma_bf16(acc[jt*2],   ph, bl0); mma_bf16(acc[jt*2],   pl, bh0);
                mma_bf16(acc[jt*2+1], ph, bh1); mma_bf16(acc[jt*2+1], ph, bl1); mma_bf16(acc[jt*2+1], pl, bh1);
            }
        }
    }
    float il0 = 1.f / l0, il1 = 1.f / l1;
    int r0 = i0 + wm + (lane >> 2);
    #pragma unroll
    for (int n = 0; n < 8; n++) {
        int c0 = h*HDD + n*8 + (lane&3)*2;
        *(float2*)&ctx[(size_t)(b*SS + r0)*DD + c0]   = make_float2(acc[n][0]*il0, acc[n][1]*il0);
        *(float2*)&ctx[(size_t)(b*SS + r0+8)*DD + c0] = make_float2(acc[n][2]*il1, acc[n][3]*il1);
    }
}

// ---- warp-per-token LayerNorm family (8 tokens/CTA, shuffle reductions) ----
#define LNW_BODY(LOAD4) \
    const int lane = threadIdx.x & 31, warp = threadIdx.x >> 5; \
    const int t = blockIdx.x*8 + warp; \
    const size_t base = (size_t)t * DD; \
    float4 v[6]; float sum = 0.f; \
    _Pragma("unroll") for (int j = 0; j < 6; j++) { int d = (lane + j*32)*4; v[j] = (LOAD4); \
        sum += v[j].x + v[j].y + v[j].z + v[j].w; } \
    _Pragma("unroll") for (int o = 16; o > 0; o >>= 1) sum += __shfl_xor_sync(~0u, sum, o); \
    float mean = sum * (1.0f/DD); \
    float vs = 0.f; \
    _Pragma("unroll") for (int j = 0; j < 6; j++) { \
        float a0=v[j].x-mean, a1=v[j].y-mean, a2=v[j].z-mean, a3=v[j].w-mean; \
        vs += a0*a0 + a1*a1 + a2*a2 + a3*a3; } \
    _Pragma("unroll") for (int o = 16; o > 0; o >>= 1) vs += __shfl_xor_sync(~0u, vs, o); \
    float rstd = rsqrtf(vs*(1.0f/DD) + 1e-12f); \
    _Pragma("unroll") for (int j = 0; j < 6; j++) { int d = (lane + j*32)*4; \
        float4 wv = *(const float4*)&w[d], bv = *(const float4*)&bb[d]; \
        float o0 = (v[j].x-mean)*rstd*wv.x + bv.x; \
        float o1 = (v[j].y-mean)*rstd*wv.y + bv.y; \
        float o2 = (v[j].z-mean)*rstd*wv.z + bv.z; \
        float o3 = (v[j].w-mean)*rstd*wv.w + bv.w; \
        *(float4*)&out[base+d] = make_float4(o0, o1, o2, o3); \
        if (oh) { uint32_t lo0, hi0 = packpair(o0, o1, lo0); \
                  uint32_t lo1, hi1 = packpair(o2, o3, lo1); \
                  *(uint2*)&oh[base+d] = make_uint2(hi0, hi1); \
                  *(uint2*)&ol[base+d] = make_uint2(lo0, lo1); } }

__global__ __launch_bounds__(256)
void embed_ln_kernel(const int* __restrict__ ids, const int* __restrict__ tts,
                     const float* __restrict__ we, const float* __restrict__ pe, const float* __restrict__ te,
                     const float* __restrict__ w, const float* __restrict__ bb, float* __restrict__ out,
                     __nv_bfloat16* __restrict__ oh, __nv_bfloat16* __restrict__ ol)
{
    const int tk = blockIdx.x*8 + (threadIdx.x >> 5);
    const float* wr = we + (size_t)ids[tk] * DD;
    const float* pr = pe + (size_t)(tk % SS) * DD;
    const float* tr = te + (size_t)tts[tk] * DD;
    LNW_BODY(make_float4(wr[d]+pr[d]+tr[d], wr[d+1]+pr[d+1]+tr[d+1],
                         wr[d+2]+pr[d+2]+tr[d+2], wr[d+3]+pr[d+3]+tr[d+3]))
}
__global__ __launch_bounds__(256)
void add_ln_kernel(const float* __restrict__ x, const float* __restrict__ y,
                   const float* __restrict__ w, const float* __restrict__ bb, float* __restrict__ out,
                   __nv_bfloat16* __restrict__ oh, __nv_bfloat16* __restrict__ ol)
{
    LNW_BODY(make_float4(x[base+d]+y[base+d], x[base+d+1]+y[base+d+1],
                         x[base+d+2]+y[base+d+2], x[base+d+3]+y[base+d+3]))
}
__global__ __launch_bounds__(256)
void add_ln3_kernel(const float* __restrict__ x1, const float* __restrict__ x2, const float* __restrict__ y,
                    const float* __restrict__ w, const float* __restrict__ bb, float* __restrict__ out,
                    __nv_bfloat16* __restrict__ oh, __nv_bfloat16* __restrict__ ol)
{
    LNW_BODY(make_float4(x1[base+d]+x2[base+d]+y[base+d], x1[base+d+1]+x2[base+d+1]+y[base+d+1],
                         x1[base+d+2]+x2[base+d+2]+y[base+d+2], x1[base+d+3]+x2[base+d+3]+y[base+d+3]))
}

// ---- metric path ----
__global__ __launch_bounds__(256)
void pool_kernel(const float* __restrict__ h, float* __restrict__ hmean)
{
    int b = blockIdx.x, c0 = blockIdx.y * 128, tid = threadIdx.x;
    int col = c0 + (tid & 127), rg = tid >> 7;
    __shared__ float part[256];
    float s = 0.f;
    for (int t = rg*256; t < rg*256 + 256; t++) s += h[((size_t)b*SS + t)*DD + col];
    part[tid] = s; __syncthreads();
    if (tid < 128) hmean[b*DD + col] = (part[tid] + part[tid+128]) * (1.0f/SS);
}
// fused cw + ginv (cw kept in smem)
__global__ __launch_bounds__(256)
void cwginv_kernel(const float* __restrict__ hmean, const float* __restrict__ Wcp,
                   const float* __restrict__ bcp,
                   const float* __restrict__ Lm_l, const float* __restrict__ diag_l,
                   float* __restrict__ ginv)
{
    int b = blockIdx.x, tid = threadIdx.x;
    __shared__ float hm[DD]; __shared__ float part[256]; __shared__ float cwsh[64];
    __shared__ float L[64][64]; __shared__ float A[64][65]; __shared__ float fcol[64];
    for (int i = tid; i < DD; i += 256) hm[i] = hmean[b*DD + i];
    __syncthreads();
    {
        int j = tid & 63, d0 = (tid >> 6) * 192;
        float acc = 0.f;
        #pragma unroll 4
        for (int d = d0; d < d0 + 192; d++) acc = fmaf(hm[d], Wcp[(size_t)d*DD + j], acc);
        part[tid] = acc;
    }
    __syncthreads();
    if (tid < 64) {
        float y = bcp[tid] + part[tid] + part[tid+64] + part[tid+128] + part[tid+192];
        cwsh[tid] = 1.f / (1.f + expf(-y));
    }
    __syncthreads();
    for (int it = 0; it < 16; it++) { int idx = it*256+tid; L[idx>>6][idx&63] = Lm_l[idx] * cwsh[idx>>6]; }
    __syncthreads();
    for (int it = 0; it < 16; it++) {
        int idx = it*256+tid, i = idx>>6, j = idx&63;
        float s = 0.f;
        for (int t2 = 0; t2 < 64; t2++) s = fmaf(L[i][t2], L[j][t2], s);
        if (i == j) s += diag_l[i] + 1e-6f + 0.1f;
        A[i][j] = s;
    }
    __syncthreads();
    for (int it = 0; it < 16; it++) { int idx = it*256+tid; L[idx>>6][idx&63] = ((idx>>6)==(idx&63)) ? 1.f : 0.f; }
    __syncthreads();
    for (int p = 0; p < 64; p++) {
        float ip = 1.f / A[p][p];
        float myf = (tid < 64) ? A[tid][p] : 0.f;
        __syncthreads();
        if (tid < 64) A[p][tid] *= ip; else if (tid < 128) L[p][tid-64] *= ip;
        if (tid < 64) fcol[tid] = (tid == p) ? 0.f : myf;
        __syncthreads();
        for (int it = 0; it < 32; it++) {
            int idx = it*256+tid, r = idx>>7, c = idx&127;
            if (r != p) { if (c < 64) A[r][c] -= fcol[r]*A[p][c]; else L[r][c-64] -= fcol[r]*L[p][c-64]; }
        }
        __syncthreads();
    }
    for (int it = 0; it < 16; it++) { int idx = it*256+tid; ginv[b*(HDD*HDD) + idx] = L[idx>>6][idx&63]; }
}

#define SYM(p, s) cudaGetSymbolAddress((void**)&p, s)

extern "C" void kernel_launch(void* const* d_in, const int* in_sizes, int n_in, void* d_out, int out_size)
{
    const int* ids = (const int*)d_in[0];
    const int* tts = (const int*)d_in[1];
    const float* we = (const float*)d_in[2];
    const float* pe = (const float*)d_in[3];
    const float* te = (const float*)d_in[4];
    const float* lnew = (const float*)d_in[5];
    const float* lneb = (const float*)d_in[6];
    const float* Wq = (const float*)d_in[7];
    const float* bq = (const float*)d_in[8];
    const float* Wk = (const float*)d_in[9];
    const float* bk = (const float*)d_in[10];
    const float* Wv = (const float*)d_in[11];
    const float* bv = (const float*)d_in[12];
    const float* Lm = (const float*)d_in[13];
    const float* dg = (const float*)d_in[14];
    const float* Wcp = (const float*)d_in[15];
    const float* bcp = (const float*)d_in[16];
    const float* Wi = (const float*)d_in[17];
    const float* bi = (const float*)d_in[18];
    const float* Wo = (const float*)d_in[19];
    const float* bo = (const float*)d_in[20];
    const float* l1w = (const float*)d_in[21];
    const float* l1b = (const float*)d_in[22];
    const float* l2w = (const float*)d_in[23];
    const float* l2b = (const float*)d_in[24];

    float *h,*ctx,*a,*o,*o2,*hmean,*ginv;
    __nv_bfloat16 *wqh,*wql,*wkh,*wkl,*wvh,*wvl,*wih,*wil,*woh,*wol;
    __nv_bfloat16 *hh,*hl,*ah,*al,*fh,*fl,*kh,*kl,*vh,*vl,*qh,*ql;
    SYM(h,g_h); SYM(ctx,g_ctx); SYM(a,g_a);
    SYM(o,g_o); SYM(o2,g_o2);
    SYM(hmean,g_hmean); SYM(ginv,g_ginv);
    SYM(wqh,g_wq_h); SYM(wql,g_wq_l); SYM(wkh,g_wk_h); SYM(wkl,g_wk_l);
    SYM(wvh,g_wv_h); SYM(wvl,g_wv_l); SYM(wih,g_wi_h); SYM(wil,g_wi_l);
    SYM(woh,g_wo_h); SYM(wol,g_wo_l);
    SYM(hh,g_hh); SYM(hl,g_hl); SYM(ah,g_ah); SYM(al,g_al); SYM(fh,g_fh); SYM(fl,g_fl);
    SYM(kh,g_kh); SYM(kl,g_kl); SYM(vh,g_vh); SYM(vl,g_vl); SYM(qh,g_qh); SYM(ql,g_ql);

    cudaFuncSetAttribute(gemm_kernel,        cudaFuncAttributeMaxDynamicSharedMemorySize, G_SMEM);
    cudaFuncSetAttribute(gemm_qkv_kernel,    cudaFuncAttributeMaxDynamicSharedMemorySize, G_SMEM);
    cudaFuncSetAttribute(gemm_splitk_kernel, cudaFuncAttributeMaxDynamicSharedMemorySize, G_SMEM);
    cudaFuncSetAttribute(flash_kernel,       cudaFuncAttributeMaxDynamicSharedMemorySize, FL_SMEM);

    split_w_kernel<<<1024, 256>>>(Wq, wqh, wql, NLL*DD*DD/4);
    split_w_kernel<<<1024, 256>>>(Wk, wkh, wkl, NLL*DD*DD/4);
    split_w_kernel<<<1024, 256>>>(Wv, wvh, wvl, NLL*DD*DD/4);
    split_w_kernel<<<2048, 256>>>(Wi, wih, wil, NLL*DD*FFF/4);
    split_w_kernel<<<2048, 256>>>(Wo, woh, wol, NLL*FFF*DD/4);

    embed_ln_kernel<<<MT/8, 256>>>(ids, tts, we, pe, te, lnew, lneb, h, hh, hl);

    for (int l = 0; l < NLL; l++) {
        size_t od = (size_t)l*DD*DD, of = (size_t)l*DD*FFF;

        gemm_qkv_kernel<<<dim3(18, 32), 256, G_SMEM>>>(hh, hl, wqh+od, wql+od, wkh+od, wkl+od,
            wvh+od, wvl+od, bq + l*DD, bk + l*DD, bv + l*DD, qh, ql, kh, kl, vh, vl);

        pool_kernel<<<dim3(BB, 6), 256>>>(h, hmean);
        cwginv_kernel<<<BB, 256>>>(hmean, Wcp + od, bcp + l*DD, Lm + (size_t)l*DD*64, dg + l*DD, ginv);

        flash_kernel<<<dim3(SS/128, BB*NHH), 256, FL_SMEM>>>(qh, ql, kh, kl, vh, vl, ginv, ctx);

        add_ln_kernel<<<MT/8, 256>>>(ctx, h, l1w + l*DD, l1b + l*DD, a, ah, al);

        gemm_kernel<<<dim3(FFF/128, 32), 256, G_SMEM>>>(ah, al, wih+of, wil+of,
            bi + (size_t)l*FFF, nullptr, fh, fl, FFF, DD, 1);
        gemm_splitk_kernel<<<dim3(DD/128, 32, 2), 256, G_SMEM>>>(fh, fl, woh+of, wol+of,
            bo + l*DD, o, o2);

        float* out_h = (l == NLL-1) ? (float*)d_out : h;
        add_ln3_kernel<<<MT/8, 256>>>(o, o2, a, l2w + l*DD, l2b + l*DD, out_h,
                                      (l == NLL-1) ? nullptr : hh, (l == NLL-1) ? nullptr : hl);
    }
}